// round 1
// baseline (speedup 1.0000x reference)
#include <cuda_runtime.h>
#include <math.h>

#define B_  2
#define T_  2048
#define C_  1024
#define H_  16
#define HD_ 64
#define N1_ 6
#define N2_ 4
#define M_  (B_*T_)   // 4096

// ---------------- scratch (no allocation allowed) ----------------
__device__ float g_qkv[(size_t)M_ * 3 * C_];          // [b*T+t][3C]
__device__ float g_q[(size_t)B_ * H_ * T_ * HD_];     // [(b*H+h)*T+t][d]
__device__ float g_k[(size_t)B_ * H_ * T_ * HD_];
__device__ float g_v[(size_t)B_ * H_ * T_ * HD_];
__device__ float g_tq[(size_t)B_ * H_ * T_];
__device__ float g_tk[(size_t)B_ * H_ * T_];
__device__ float g_y[(size_t)M_ * C_];                // attn out, [b*T+t][C]

// ---------------- SGEMM: C[m,n] = sum_k A[m,k]*B[n,k] (+bias) ----------------
// A: [M,K] row-major, Bm: [N,K] row-major. 128x128x8 tiles, 8x8 per thread.
template<bool BIAS>
__global__ __launch_bounds__(256) void sgemm_nt(
    const float* __restrict__ A, const float* __restrict__ Bm,
    const float* __restrict__ bias, float* __restrict__ Cm,
    int M, int N, int K)
{
    __shared__ float As[8][128];
    __shared__ float Bs[8][128];
    const int bm = blockIdx.y * 128, bn = blockIdx.x * 128;
    const int tid = threadIdx.x;
    const int tx = tid & 15, ty = tid >> 4;
    const int lr = tid >> 1;           // 0..127
    const int lk = (tid & 1) * 4;      // 0 or 4

    float acc[8][8];
    #pragma unroll
    for (int i = 0; i < 8; i++)
        #pragma unroll
        for (int j = 0; j < 8; j++) acc[i][j] = 0.0f;

    const float* Aptr = A + (size_t)(bm + lr) * K + lk;
    const float* Bptr = Bm + (size_t)(bn + lr) * K + lk;

    for (int k0 = 0; k0 < K; k0 += 8) {
        float4 a4 = *(const float4*)(Aptr + k0);
        float4 b4 = *(const float4*)(Bptr + k0);
        __syncthreads();
        As[lk+0][lr] = a4.x; As[lk+1][lr] = a4.y; As[lk+2][lr] = a4.z; As[lk+3][lr] = a4.w;
        Bs[lk+0][lr] = b4.x; Bs[lk+1][lr] = b4.y; Bs[lk+2][lr] = b4.z; Bs[lk+3][lr] = b4.w;
        __syncthreads();
        #pragma unroll
        for (int kk = 0; kk < 8; kk++) {
            float ar[8], br[8];
            #pragma unroll
            for (int i = 0; i < 8; i++) ar[i] = As[kk][ty*8 + i];
            #pragma unroll
            for (int j = 0; j < 8; j++) br[j] = Bs[kk][tx*8 + j];
            #pragma unroll
            for (int i = 0; i < 8; i++)
                #pragma unroll
                for (int j = 0; j < 8; j++)
                    acc[i][j] = fmaf(ar[i], br[j], acc[i][j]);
        }
    }

    #pragma unroll
    for (int i = 0; i < 8; i++) {
        const int row = bm + ty*8 + i;
        #pragma unroll
        for (int j = 0; j < 8; j += 4) {
            const int col = bn + tx*8 + j;
            float4 r;
            r.x = acc[i][j+0]; r.y = acc[i][j+1]; r.z = acc[i][j+2]; r.w = acc[i][j+3];
            if (BIAS) { r.x += bias[col]; r.y += bias[col+1]; r.z += bias[col+2]; r.w += bias[col+3]; }
            *(float4*)(Cm + (size_t)row * N + col) = r;
        }
    }
}

// ---------------- rotary + split + per-head-group preprocessing ----------------
// one warp per (b,h,t) row; lane d handles elements d and d+32
__global__ __launch_bounds__(256) void rotary_kernel(
    const float* __restrict__ qkv, const float* __restrict__ curv)
{
    const int warp = threadIdx.x >> 5, lane = threadIdx.x & 31;
    const int row = blockIdx.x * 8 + warp;   // (b*H + h)*T + t
    const int t = row % T_;
    const int h = (row / T_) % H_;
    const int b = row / (T_ * H_);

    const float* src = qkv + (size_t)(b * T_ + t) * (3 * C_) + h * HD_ + lane;
    float q0 = src[0],        q1 = src[32];
    float k0 = src[C_],       k1 = src[C_ + 32];
    float v0 = src[2 * C_],   v1 = src[2 * C_ + 32];

    // inv_freq = 10000^{-2*lane/64}
    const float LOG2_1E4 = 13.287712379549449f;
    float inv_freq = exp2f(-(float)lane * (LOG2_1E4 / 32.0f));
    float fr = (float)t * inv_freq;
    float sn, cs;
    sincosf(fr, &sn, &cs);

    float qa = fmaf(q0, cs,  q1 * sn);
    float qb = fmaf(q1, cs, -q0 * sn);
    float ka = fmaf(k0, cs,  k1 * sn);
    float kb = fmaf(k1, cs, -k0 * sn);

    float sq = qa*qa + qb*qb;
    float sk = ka*ka + kb*kb;
    #pragma unroll
    for (int off = 16; off; off >>= 1) {
        sq += __shfl_xor_sync(0xffffffffu, sq, off);
        sk += __shfl_xor_sync(0xffffffffu, sk, off);
    }

    if (h >= N1_ + N2_) {
        // unit-normalize q,k
        float nq = 1.0f / fmaxf(sqrtf(sq), 1e-12f);
        float nk = 1.0f / fmaxf(sqrtf(sk), 1e-12f);
        qa *= nq; qb *= nq; ka *= nk; kb *= nk;
    } else if (h >= N1_) {
        if (lane == 0) {
            float c = curv[h - N1_];
            g_tq[row] = sqrtf(1.0f / c + sq);
            g_tk[row] = sqrtf(1.0f / c + sk);
        }
    }

    const size_t o = (size_t)row * HD_ + lane;
    g_q[o] = qa; g_q[o + 32] = qb;
    g_k[o] = ka; g_k[o + 32] = kb;
    g_v[o] = v0; g_v[o + 32] = v1;
}

// ---------------- flash attention, 3 score geometries ----------------
// grid: (T/64, B*H); block 64 threads; thread owns one query row.
__global__ __launch_bounds__(64) void flash_kernel(
    const float* __restrict__ curv, float* __restrict__ y)
{
    __shared__ float4 ksh4[64 * 16];   // 64 keys x 64 dims
    __shared__ float4 vsh4[64 * 16];
    __shared__ float  ssh[64][33];     // scores, 32-key chunk, padded
    __shared__ float  tksh[64];

    const int bh  = blockIdx.y;        // b*H + h
    const int h   = bh % H_;
    const int qt  = blockIdx.x;
    const int tid = threadIdx.x;
    const int qi  = qt * 64 + tid;
    const int mode = (h < N1_) ? 0 : (h < N1_ + N2_ ? 1 : 2);

    float qreg[64];
    {
        const float4* qp = (const float4*)(g_q + ((size_t)bh * T_ + qi) * HD_);
        #pragma unroll
        for (int i = 0; i < 16; i++) {
            float4 f = qp[i];
            qreg[4*i] = f.x; qreg[4*i+1] = f.y; qreg[4*i+2] = f.z; qreg[4*i+3] = f.w;
        }
    }

    const float scale = (mode == 0) ? 0.125f : 8.0f;
    float cu = 1.0f, rcinv = 1.0f, my_tq = 0.0f;
    if (mode == 1) {
        cu = curv[h - N1_];
        rcinv = sqrtf(1.0f / cu);
        my_tq = g_tq[(size_t)bh * T_ + qi];
    }

    float m = -INFINITY, l = 0.0f;
    float o[64];
    #pragma unroll
    for (int d = 0; d < 64; d++) o[d] = 0.0f;

    for (int kt = 0; kt <= qt; kt++) {
        __syncthreads();
        const float4* kg = (const float4*)(g_k + ((size_t)bh * T_ + kt * 64) * HD_);
        const float4* vg = (const float4*)(g_v + ((size_t)bh * T_ + kt * 64) * HD_);
        #pragma unroll
        for (int i = 0; i < 16; i++) {
            ksh4[tid + i * 64] = kg[tid + i * 64];
            vsh4[tid + i * 64] = vg[tid + i * 64];
        }
        if (mode == 1) tksh[tid] = g_tk[(size_t)bh * T_ + kt * 64 + tid];
        __syncthreads();

        const int nvalid = (kt == qt) ? (tid + 1) : 64;

        for (int c0 = 0; c0 < 64; c0 += 32) {
            int jmax = nvalid - c0;
            if (jmax <= 0) break;
            if (jmax > 32) jmax = 32;

            float smax = -INFINITY;
            for (int j = 0; j < jmax; j++) {
                const float4* kr = ksh4 + (c0 + j) * 16;
                float d0 = 0.f, d1 = 0.f, d2 = 0.f, d3 = 0.f;
                #pragma unroll
                for (int d4 = 0; d4 < 16; d4++) {
                    float4 kk = kr[d4];
                    d0 = fmaf(qreg[4*d4+0], kk.x, d0);
                    d1 = fmaf(qreg[4*d4+1], kk.y, d1);
                    d2 = fmaf(qreg[4*d4+2], kk.z, d2);
                    d3 = fmaf(qreg[4*d4+3], kk.w, d3);
                }
                float dot = (d0 + d1) + (d2 + d3);
                float s;
                if (mode == 1) {
                    // arg-1 = c*(tq*tk - dot) - 1  (>= 1e-7 by clamp)
                    float am1 = fmaxf(cu * (my_tq * tksh[c0 + j] - dot) - 1.0f, 1e-7f);
                    // arccosh(arg) = log(arg + sqrt((arg-1)(arg+1)))
                    float dis = rcinv * logf((am1 + 1.0f) + sqrtf(am1 * (am1 + 2.0f)));
                    s = 1.0f / (1e-6f + dis);
                } else {
                    s = dot * scale;
                }
                ssh[tid][j] = s;
                smax = fmaxf(smax, s);
            }

            float mnew = fmaxf(m, smax);
            float corr = __expf(m - mnew);   // exp(-inf)=0 on first chunk
            l *= corr;
            #pragma unroll
            for (int d = 0; d < 64; d++) o[d] *= corr;

            for (int j = 0; j < jmax; j++) {
                float p = __expf(ssh[tid][j] - mnew);
                l += p;
                const float4* vr = vsh4 + (c0 + j) * 16;
                #pragma unroll
                for (int d4 = 0; d4 < 16; d4++) {
                    float4 vv = vr[d4];
                    o[4*d4+0] = fmaf(p, vv.x, o[4*d4+0]);
                    o[4*d4+1] = fmaf(p, vv.y, o[4*d4+1]);
                    o[4*d4+2] = fmaf(p, vv.z, o[4*d4+2]);
                    o[4*d4+3] = fmaf(p, vv.w, o[4*d4+3]);
                }
            }
            m = mnew;
        }
    }

    const int b = bh / H_;
    const float inv_l = 1.0f / l;
    float4* yp = (float4*)(g_y + (size_t)(b * T_ + qi) * C_ + h * HD_);
    #pragma unroll
    for (int i = 0; i < 16; i++) {
        float4 r;
        r.x = o[4*i+0] * inv_l; r.y = o[4*i+1] * inv_l;
        r.z = o[4*i+2] * inv_l; r.w = o[4*i+3] * inv_l;
        yp[i] = r;
    }
}

// ---------------- launch ----------------
extern "C" void kernel_launch(void* const* d_in, const int* in_sizes, int n_in,
                              void* d_out, int out_size)
{
    const float* x      = (const float*)d_in[0];
    const float* qkv_w  = (const float*)d_in[1];
    const float* proj_w = (const float*)d_in[2];
    const float* proj_b = (const float*)d_in[3];
    const float* curv   = (const float*)d_in[4];
    float* out = (float*)d_out;

    void *pqkv = nullptr, *py = nullptr;
    cudaGetSymbolAddress(&pqkv, g_qkv);
    cudaGetSymbolAddress(&py, g_y);

    // 1) qkv = x @ qkv_w^T   [4096,3072]
    sgemm_nt<false><<<dim3(3 * C_ / 128, M_ / 128), 256>>>(
        x, qkv_w, nullptr, (float*)pqkv, M_, 3 * C_, C_);

    // 2) rotary + split + normalize/tq-tk
    rotary_kernel<<<(B_ * H_ * T_) / 8, 256>>>((const float*)pqkv, curv);

    // 3) attention (3 geometries) -> g_y [4096,1024]
    flash_kernel<<<dim3(T_ / 64, B_ * H_), 64>>>(curv, (float*)py);

    // 4) out = y @ proj_w^T + proj_b
    sgemm_nt<true><<<dim3(C_ / 128, M_ / 128), 256>>>(
        (const float*)py, proj_w, proj_b, out, M_, C_, C_);
}

// round 3
// speedup vs baseline: 1.3580x; 1.3580x over previous
#include <cuda_runtime.h>
#include <math.h>
#include <stdint.h>

#define B_  2
#define T_  2048
#define C_  1024
#define H_  16
#define HD_ 64
#define N1_ 6
#define N2_ 4
#define M_  (B_*T_)   // 4096

// ---------------- scratch (no allocation allowed) ----------------
__device__ float g_qkv[(size_t)M_ * 3 * C_];          // [b*T+t][3C]
__device__ float g_q[(size_t)B_ * H_ * T_ * HD_];     // [(b*H+h)*T+t][d]
__device__ float g_k[(size_t)B_ * H_ * T_ * HD_];
__device__ float g_v[(size_t)B_ * H_ * T_ * HD_];
__device__ float g_tq[(size_t)B_ * H_ * T_];
__device__ float g_tk[(size_t)B_ * H_ * T_];
__device__ float g_y[(size_t)M_ * C_];                // attn out, [b*T+t][C]

// ---------------- tf32 helpers ----------------
__device__ __forceinline__ uint32_t f2tf32(float f) {
    uint32_t u;
    asm("cvt.rna.tf32.f32 %0, %1;" : "=r"(u) : "f"(f));
    return u;
}

__device__ __forceinline__ void mma_tf32(float& c0, float& c1, float& c2, float& c3,
                                         uint32_t a0, uint32_t a1, uint32_t a2, uint32_t a3,
                                         uint32_t b0, uint32_t b1) {
    asm volatile(
        "mma.sync.aligned.m16n8k8.row.col.f32.tf32.tf32.f32 "
        "{%0,%1,%2,%3}, {%4,%5,%6,%7}, {%8,%9}, {%0,%1,%2,%3};"
        : "+f"(c0), "+f"(c1), "+f"(c2), "+f"(c3)
        : "r"(a0), "r"(a1), "r"(a2), "r"(a3), "r"(b0), "r"(b1));
}

// ================= tf32 mma.sync GEMM: C[m,n] = sum_k A[m,k]*B[n,k] (+bias) ====
// 128x128 CTA tile, 8 warps (2x4), warp tile 64x32, K chunk 32.
// Smem rows padded to 36 floats: fragment loads conflict-free, v4 stores aligned.
#define SPAD 36

template<bool BIAS>
__global__ __launch_bounds__(256) void mma_gemm(
    const float* __restrict__ A, const float* __restrict__ Bm,
    const float* __restrict__ bias, float* __restrict__ Cm,
    int M, int N, int K)
{
    __shared__ uint32_t As[128][SPAD];
    __shared__ uint32_t Bs[128][SPAD];

    const int tid = threadIdx.x;
    const int wid = tid >> 5, lane = tid & 31;
    const int g = lane >> 2, tig = lane & 3;       // group / thread-in-group
    const int warp_m = wid >> 2, warp_n = wid & 3; // 2 x 4
    const int bm = blockIdx.y * 128, bn = blockIdx.x * 128;

    // gmem loader coords: row r (0..127), 16 floats starting at cq
    const int r  = tid >> 1;
    const int cq = (tid & 1) * 16;
    const float* Ap = A + (size_t)(bm + r) * K + cq;
    const float* Bp = Bm + (size_t)(bn + r) * K + cq;

    float acc[4][4][4];
    #pragma unroll
    for (int i = 0; i < 4; i++)
        #pragma unroll
        for (int j = 0; j < 4; j++)
            #pragma unroll
            for (int q = 0; q < 4; q++) acc[i][j][q] = 0.0f;

    const int nk = K >> 5;
    float4 ar[4], br[4];
    #pragma unroll
    for (int j = 0; j < 4; j++) {
        ar[j] = *(const float4*)(Ap + 4 * j);
        br[j] = *(const float4*)(Bp + 4 * j);
    }

    for (int i = 0; i < nk; i++) {
        __syncthreads();
        #pragma unroll
        for (int j = 0; j < 4; j++) {
            As[r][cq + 4*j + 0] = f2tf32(ar[j].x);
            As[r][cq + 4*j + 1] = f2tf32(ar[j].y);
            As[r][cq + 4*j + 2] = f2tf32(ar[j].z);
            As[r][cq + 4*j + 3] = f2tf32(ar[j].w);
            Bs[r][cq + 4*j + 0] = f2tf32(br[j].x);
            Bs[r][cq + 4*j + 1] = f2tf32(br[j].y);
            Bs[r][cq + 4*j + 2] = f2tf32(br[j].z);
            Bs[r][cq + 4*j + 3] = f2tf32(br[j].w);
        }
        __syncthreads();

        if (i + 1 < nk) {
            const int koff = (i + 1) * 32;
            #pragma unroll
            for (int j = 0; j < 4; j++) {
                ar[j] = *(const float4*)(Ap + koff + 4 * j);
                br[j] = *(const float4*)(Bp + koff + 4 * j);
            }
        }

        #pragma unroll
        for (int kk = 0; kk < 4; kk++) {
            const int k0 = kk * 8;
            uint32_t afr[4][4], bfr[4][2];
            #pragma unroll
            for (int mf = 0; mf < 4; mf++) {
                const int rowb = warp_m * 64 + mf * 16;
                afr[mf][0] = As[rowb + g    ][k0 + tig];
                afr[mf][1] = As[rowb + 8 + g][k0 + tig];
                afr[mf][2] = As[rowb + g    ][k0 + tig + 4];
                afr[mf][3] = As[rowb + 8 + g][k0 + tig + 4];
            }
            #pragma unroll
            for (int nf = 0; nf < 4; nf++) {
                const int colb = warp_n * 32 + nf * 8;
                bfr[nf][0] = Bs[colb + g][k0 + tig];
                bfr[nf][1] = Bs[colb + g][k0 + tig + 4];
            }
            #pragma unroll
            for (int mf = 0; mf < 4; mf++)
                #pragma unroll
                for (int nf = 0; nf < 4; nf++)
                    mma_tf32(acc[mf][nf][0], acc[mf][nf][1], acc[mf][nf][2], acc[mf][nf][3],
                             afr[mf][0], afr[mf][1], afr[mf][2], afr[mf][3],
                             bfr[nf][0], bfr[nf][1]);
        }
    }

    // epilogue: c0,c1 at (row, col..col+1), c2,c3 at (row+8, col..col+1)
    #pragma unroll
    for (int mf = 0; mf < 4; mf++) {
        const int row0 = bm + warp_m * 64 + mf * 16 + g;
        #pragma unroll
        for (int nf = 0; nf < 4; nf++) {
            const int col = bn + warp_n * 32 + nf * 8 + tig * 2;
            float b0 = 0.f, b1 = 0.f;
            if (BIAS) { b0 = bias[col]; b1 = bias[col + 1]; }
            float2 v0, v1;
            v0.x = acc[mf][nf][0] + b0; v0.y = acc[mf][nf][1] + b1;
            v1.x = acc[mf][nf][2] + b0; v1.y = acc[mf][nf][3] + b1;
            *(float2*)(Cm + (size_t)row0 * N + col)       = v0;
            *(float2*)(Cm + (size_t)(row0 + 8) * N + col) = v1;
        }
    }
}

// ---------------- rotary + split + per-head-group preprocessing ----------------
__global__ __launch_bounds__(256) void rotary_kernel(
    const float* __restrict__ qkv, const float* __restrict__ curv)
{
    const int warp = threadIdx.x >> 5, lane = threadIdx.x & 31;
    const int row = blockIdx.x * 8 + warp;   // (b*H + h)*T + t
    const int t = row % T_;
    const int h = (row / T_) % H_;
    const int b = row / (T_ * H_);

    const float* src = qkv + (size_t)(b * T_ + t) * (3 * C_) + h * HD_ + lane;
    float q0 = src[0],        q1 = src[32];
    float k0 = src[C_],       k1 = src[C_ + 32];
    float v0 = src[2 * C_],   v1 = src[2 * C_ + 32];

    const float LOG2_1E4 = 13.287712379549449f;
    float inv_freq = exp2f(-(float)lane * (LOG2_1E4 / 32.0f));
    float fr = (float)t * inv_freq;
    float sn, cs;
    sincosf(fr, &sn, &cs);

    float qa = fmaf(q0, cs,  q1 * sn);
    float qb = fmaf(q1, cs, -q0 * sn);
    float ka = fmaf(k0, cs,  k1 * sn);
    float kb = fmaf(k1, cs, -k0 * sn);

    float sq = qa*qa + qb*qb;
    float sk = ka*ka + kb*kb;
    #pragma unroll
    for (int off = 16; off; off >>= 1) {
        sq += __shfl_xor_sync(0xffffffffu, sq, off);
        sk += __shfl_xor_sync(0xffffffffu, sk, off);
    }

    if (h >= N1_ + N2_) {
        float nq = 1.0f / fmaxf(sqrtf(sq), 1e-12f);
        float nk = 1.0f / fmaxf(sqrtf(sk), 1e-12f);
        qa *= nq; qb *= nq; ka *= nk; kb *= nk;
    } else if (h >= N1_) {
        if (lane == 0) {
            float c = curv[h - N1_];
            g_tq[row] = sqrtf(1.0f / c + sq);
            g_tk[row] = sqrtf(1.0f / c + sk);
        }
    }

    const size_t o = (size_t)row * HD_ + lane;
    g_q[o] = qa; g_q[o + 32] = qb;
    g_k[o] = ka; g_k[o + 32] = kb;
    g_v[o] = v0; g_v[o + 32] = v1;
}

// ---------------- flash attention, 3 score geometries ----------------
__global__ __launch_bounds__(64) void flash_kernel(
    const float* __restrict__ curv, float* __restrict__ y)
{
    __shared__ float4 ksh4[64 * 16];
    __shared__ float4 vsh4[64 * 16];
    __shared__ float  ssh[64][33];
    __shared__ float  tksh[64];

    const int bh  = blockIdx.y;
    const int h   = bh % H_;
    const int qt  = blockIdx.x;
    const int tid = threadIdx.x;
    const int qi  = qt * 64 + tid;
    const int mode = (h < N1_) ? 0 : (h < N1_ + N2_ ? 1 : 2);

    float qreg[64];
    {
        const float4* qp = (const float4*)(g_q + ((size_t)bh * T_ + qi) * HD_);
        #pragma unroll
        for (int i = 0; i < 16; i++) {
            float4 f = qp[i];
            qreg[4*i] = f.x; qreg[4*i+1] = f.y; qreg[4*i+2] = f.z; qreg[4*i+3] = f.w;
        }
    }

    const float scale = (mode == 0) ? 0.125f : 8.0f;
    float cu = 1.0f, rcinv = 1.0f, my_tq = 0.0f;
    if (mode == 1) {
        cu = curv[h - N1_];
        rcinv = sqrtf(1.0f / cu);
        my_tq = g_tq[(size_t)bh * T_ + qi];
    }

    float m = -INFINITY, l = 0.0f;
    float o[64];
    #pragma unroll
    for (int d = 0; d < 64; d++) o[d] = 0.0f;

    for (int kt = 0; kt <= qt; kt++) {
        __syncthreads();
        const float4* kg = (const float4*)(g_k + ((size_t)bh * T_ + kt * 64) * HD_);
        const float4* vg = (const float4*)(g_v + ((size_t)bh * T_ + kt * 64) * HD_);
        #pragma unroll
        for (int i = 0; i < 16; i++) {
            ksh4[tid + i * 64] = kg[tid + i * 64];
            vsh4[tid + i * 64] = vg[tid + i * 64];
        }
        if (mode == 1) tksh[tid] = g_tk[(size_t)bh * T_ + kt * 64 + tid];
        __syncthreads();

        const int nvalid = (kt == qt) ? (tid + 1) : 64;

        for (int c0 = 0; c0 < 64; c0 += 32) {
            int jmax = nvalid - c0;
            if (jmax <= 0) break;
            if (jmax > 32) jmax = 32;

            float smax = -INFINITY;
            for (int j = 0; j < jmax; j++) {
                const float4* kr = ksh4 + (c0 + j) * 16;
                float d0 = 0.f, d1 = 0.f, d2 = 0.f, d3 = 0.f;
                #pragma unroll
                for (int d4 = 0; d4 < 16; d4++) {
                    float4 kk = kr[d4];
                    d0 = fmaf(qreg[4*d4+0], kk.x, d0);
                    d1 = fmaf(qreg[4*d4+1], kk.y, d1);
                    d2 = fmaf(qreg[4*d4+2], kk.z, d2);
                    d3 = fmaf(qreg[4*d4+3], kk.w, d3);
                }
                float dot = (d0 + d1) + (d2 + d3);
                float s;
                if (mode == 1) {
                    float am1 = fmaxf(cu * (my_tq * tksh[c0 + j] - dot) - 1.0f, 1e-7f);
                    float dis = rcinv * logf((am1 + 1.0f) + sqrtf(am1 * (am1 + 2.0f)));
                    s = 1.0f / (1e-6f + dis);
                } else {
                    s = dot * scale;
                }
                ssh[tid][j] = s;
                smax = fmaxf(smax, s);
            }

            float mnew = fmaxf(m, smax);
            float corr = __expf(m - mnew);
            l *= corr;
            #pragma unroll
            for (int d = 0; d < 64; d++) o[d] *= corr;

            for (int j = 0; j < jmax; j++) {
                float p = __expf(ssh[tid][j] - mnew);
                l += p;
                const float4* vr = vsh4 + (c0 + j) * 16;
                #pragma unroll
                for (int d4 = 0; d4 < 16; d4++) {
                    float4 vv = vr[d4];
                    o[4*d4+0] = fmaf(p, vv.x, o[4*d4+0]);
                    o[4*d4+1] = fmaf(p, vv.y, o[4*d4+1]);
                    o[4*d4+2] = fmaf(p, vv.z, o[4*d4+2]);
                    o[4*d4+3] = fmaf(p, vv.w, o[4*d4+3]);
                }
            }
            m = mnew;
        }
    }

    const int b = bh / H_;
    const float inv_l = 1.0f / l;
    float4* yp = (float4*)(g_y + (size_t)(b * T_ + qi) * C_ + h * HD_);
    #pragma unroll
    for (int i = 0; i < 16; i++) {
        float4 r;
        r.x = o[4*i+0] * inv_l; r.y = o[4*i+1] * inv_l;
        r.z = o[4*i+2] * inv_l; r.w = o[4*i+3] * inv_l;
        yp[i] = r;
    }
}

// ---------------- launch ----------------
extern "C" void kernel_launch(void* const* d_in, const int* in_sizes, int n_in,
                              void* d_out, int out_size)
{
    const float* x      = (const float*)d_in[0];
    const float* qkv_w  = (const float*)d_in[1];
    const float* proj_w = (const float*)d_in[2];
    const float* proj_b = (const float*)d_in[3];
    const float* curv   = (const float*)d_in[4];
    float* out = (float*)d_out;

    void *pqkv = nullptr, *py = nullptr;
    cudaGetSymbolAddress(&pqkv, g_qkv);
    cudaGetSymbolAddress(&py, g_y);

    // 1) qkv = x @ qkv_w^T   [4096,3072]
    mma_gemm<false><<<dim3(3 * C_ / 128, M_ / 128), 256>>>(
        x, qkv_w, nullptr, (float*)pqkv, M_, 3 * C_, C_);

    // 2) rotary + split + normalize/tq-tk
    rotary_kernel<<<(B_ * H_ * T_) / 8, 256>>>((const float*)pqkv, curv);

    // 3) attention (3 geometries) -> g_y [4096,1024]
    flash_kernel<<<dim3(T_ / 64, B_ * H_), 64>>>(curv, (float*)py);

    // 4) out = y @ proj_w^T + proj_b
    mma_gemm<true><<<dim3(C_ / 128, M_ / 128), 256>>>(
        (const float*)py, proj_w, proj_b, out, M_, C_, C_);
}

// round 4
// speedup vs baseline: 1.9551x; 1.4397x over previous
#include <cuda_runtime.h>
#include <math.h>
#include <stdint.h>

#define B_  2
#define T_  2048
#define C_  1024
#define H_  16
#define HD_ 64
#define N1_ 6
#define N2_ 4
#define M_  (B_*T_)   // 4096

// ---------------- scratch (no allocation allowed) ----------------
__device__ float g_qkv[(size_t)M_ * 3 * C_];
__device__ float g_q[(size_t)B_ * H_ * T_ * HD_];
__device__ float g_k[(size_t)B_ * H_ * T_ * HD_];
__device__ float g_v[(size_t)B_ * H_ * T_ * HD_];
__device__ float g_tq[(size_t)B_ * H_ * T_];
__device__ float g_tk[(size_t)B_ * H_ * T_];
__device__ float g_y[(size_t)M_ * C_];

// ---------------- tf32 helpers ----------------
__device__ __forceinline__ uint32_t f2tf32(float f) {
    uint32_t u;
    asm("cvt.rna.tf32.f32 %0, %1;" : "=r"(u) : "f"(f));
    return u;
}
__device__ __forceinline__ void mma_tf32(float& c0, float& c1, float& c2, float& c3,
                                         uint32_t a0, uint32_t a1, uint32_t a2, uint32_t a3,
                                         uint32_t b0, uint32_t b1) {
    asm volatile(
        "mma.sync.aligned.m16n8k8.row.col.f32.tf32.tf32.f32 "
        "{%0,%1,%2,%3}, {%4,%5,%6,%7}, {%8,%9}, {%0,%1,%2,%3};"
        : "+f"(c0), "+f"(c1), "+f"(c2), "+f"(c3)
        : "r"(a0), "r"(a1), "r"(a2), "r"(a3), "r"(b0), "r"(b1));
}

// ================= tf32 mma.sync GEMM (as in R3, passing) ====
#define SPAD 36
template<bool BIAS>
__global__ __launch_bounds__(256) void mma_gemm(
    const float* __restrict__ A, const float* __restrict__ Bm,
    const float* __restrict__ bias, float* __restrict__ Cm,
    int M, int N, int K)
{
    __shared__ uint32_t As[128][SPAD];
    __shared__ uint32_t Bs[128][SPAD];

    const int tid = threadIdx.x;
    const int wid = tid >> 5, lane = tid & 31;
    const int g = lane >> 2, tig = lane & 3;
    const int warp_m = wid >> 2, warp_n = wid & 3;
    const int bm = blockIdx.y * 128, bn = blockIdx.x * 128;

    const int r  = tid >> 1;
    const int cq = (tid & 1) * 16;
    const float* Ap = A + (size_t)(bm + r) * K + cq;
    const float* Bp = Bm + (size_t)(bn + r) * K + cq;

    float acc[4][4][4];
    #pragma unroll
    for (int i = 0; i < 4; i++)
        #pragma unroll
        for (int j = 0; j < 4; j++)
            #pragma unroll
            for (int q = 0; q < 4; q++) acc[i][j][q] = 0.0f;

    const int nk = K >> 5;
    float4 ar[4], br[4];
    #pragma unroll
    for (int j = 0; j < 4; j++) {
        ar[j] = *(const float4*)(Ap + 4 * j);
        br[j] = *(const float4*)(Bp + 4 * j);
    }

    for (int i = 0; i < nk; i++) {
        __syncthreads();
        #pragma unroll
        for (int j = 0; j < 4; j++) {
            As[r][cq + 4*j + 0] = f2tf32(ar[j].x);
            As[r][cq + 4*j + 1] = f2tf32(ar[j].y);
            As[r][cq + 4*j + 2] = f2tf32(ar[j].z);
            As[r][cq + 4*j + 3] = f2tf32(ar[j].w);
            Bs[r][cq + 4*j + 0] = f2tf32(br[j].x);
            Bs[r][cq + 4*j + 1] = f2tf32(br[j].y);
            Bs[r][cq + 4*j + 2] = f2tf32(br[j].z);
            Bs[r][cq + 4*j + 3] = f2tf32(br[j].w);
        }
        __syncthreads();

        if (i + 1 < nk) {
            const int koff = (i + 1) * 32;
            #pragma unroll
            for (int j = 0; j < 4; j++) {
                ar[j] = *(const float4*)(Ap + koff + 4 * j);
                br[j] = *(const float4*)(Bp + koff + 4 * j);
            }
        }

        #pragma unroll
        for (int kk = 0; kk < 4; kk++) {
            const int k0 = kk * 8;
            uint32_t afr[4][4], bfr[4][2];
            #pragma unroll
            for (int mf = 0; mf < 4; mf++) {
                const int rowb = warp_m * 64 + mf * 16;
                afr[mf][0] = As[rowb + g    ][k0 + tig];
                afr[mf][1] = As[rowb + 8 + g][k0 + tig];
                afr[mf][2] = As[rowb + g    ][k0 + tig + 4];
                afr[mf][3] = As[rowb + 8 + g][k0 + tig + 4];
            }
            #pragma unroll
            for (int nf = 0; nf < 4; nf++) {
                const int colb = warp_n * 32 + nf * 8;
                bfr[nf][0] = Bs[colb + g][k0 + tig];
                bfr[nf][1] = Bs[colb + g][k0 + tig + 4];
            }
            #pragma unroll
            for (int mf = 0; mf < 4; mf++)
                #pragma unroll
                for (int nf = 0; nf < 4; nf++)
                    mma_tf32(acc[mf][nf][0], acc[mf][nf][1], acc[mf][nf][2], acc[mf][nf][3],
                             afr[mf][0], afr[mf][1], afr[mf][2], afr[mf][3],
                             bfr[nf][0], bfr[nf][1]);
        }
    }

    #pragma unroll
    for (int mf = 0; mf < 4; mf++) {
        const int row0 = bm + warp_m * 64 + mf * 16 + g;
        #pragma unroll
        for (int nf = 0; nf < 4; nf++) {
            const int col = bn + warp_n * 32 + nf * 8 + tig * 2;
            float b0 = 0.f, b1 = 0.f;
            if (BIAS) { b0 = bias[col]; b1 = bias[col + 1]; }
            float2 v0, v1;
            v0.x = acc[mf][nf][0] + b0; v0.y = acc[mf][nf][1] + b1;
            v1.x = acc[mf][nf][2] + b0; v1.y = acc[mf][nf][3] + b1;
            *(float2*)(Cm + (size_t)row0 * N + col)       = v0;
            *(float2*)(Cm + (size_t)(row0 + 8) * N + col) = v1;
        }
    }
}

// ---------------- rotary + split + per-head-group preprocessing ----------------
__global__ __launch_bounds__(256) void rotary_kernel(
    const float* __restrict__ qkv, const float* __restrict__ curv)
{
    const int warp = threadIdx.x >> 5, lane = threadIdx.x & 31;
    const int row = blockIdx.x * 8 + warp;
    const int t = row % T_;
    const int h = (row / T_) % H_;
    const int b = row / (T_ * H_);

    const float* src = qkv + (size_t)(b * T_ + t) * (3 * C_) + h * HD_ + lane;
    float q0 = src[0],        q1 = src[32];
    float k0 = src[C_],       k1 = src[C_ + 32];
    float v0 = src[2 * C_],   v1 = src[2 * C_ + 32];

    const float LOG2_1E4 = 13.287712379549449f;
    float inv_freq = exp2f(-(float)lane * (LOG2_1E4 / 32.0f));
    float fr = (float)t * inv_freq;
    float sn, cs;
    sincosf(fr, &sn, &cs);

    float qa = fmaf(q0, cs,  q1 * sn);
    float qb = fmaf(q1, cs, -q0 * sn);
    float ka = fmaf(k0, cs,  k1 * sn);
    float kb = fmaf(k1, cs, -k0 * sn);

    float sq = qa*qa + qb*qb;
    float sk = ka*ka + kb*kb;
    #pragma unroll
    for (int off = 16; off; off >>= 1) {
        sq += __shfl_xor_sync(0xffffffffu, sq, off);
        sk += __shfl_xor_sync(0xffffffffu, sk, off);
    }

    if (h >= N1_ + N2_) {
        float nq = 1.0f / fmaxf(sqrtf(sq), 1e-12f);
        float nk = 1.0f / fmaxf(sqrtf(sk), 1e-12f);
        qa *= nq; qb *= nq; ka *= nk; kb *= nk;
    } else if (h >= N1_) {
        if (lane == 0) {
            float c = curv[h - N1_];
            g_tq[row] = sqrtf(1.0f / c + sq);
            g_tk[row] = sqrtf(1.0f / c + sk);
        }
    }

    const size_t o = (size_t)row * HD_ + lane;
    g_q[o] = qa; g_q[o + 32] = qb;
    g_k[o] = ka; g_k[o + 32] = kb;
    g_v[o] = v0; g_v[o + 32] = v1;
}

// ---------------- fused flash: tensor path (modes 0,2) + fp32 path (mode 1) ----
// grid (T/64, B*H), 128 threads.
// dyn smem layout (bytes):
//  tensor: Qs[64][68]u32 @0, Ks @17408, Vt @34816, Ps @52224   (69632 total)
//  mode1 : kb float4[2][1024] @0, vb @32768, ssh[128][17] @65536,
//          tk2[2][64] @74240 ; merge: obuf[64][68] @0, msh @32768, lsh @32768+256
#define FSM_BYTES 74752

__global__ __launch_bounds__(128) void flash_fused(const float* __restrict__ curv)
{
    extern __shared__ char dsm[];
    const int bh = blockIdx.y, qt = blockIdx.x, tid = threadIdx.x;
    const int h = bh % H_, b = bh / H_;
    const int mode = (h < N1_) ? 0 : (h < N1_ + N2_ ? 1 : 2);

    if (mode != 1) {
        // ================= tensor-core path =================
        uint32_t (*Qs)[68] = (uint32_t(*)[68])(dsm);
        uint32_t (*Ks)[68] = (uint32_t(*)[68])(dsm + 17408);
        uint32_t (*Vt)[68] = (uint32_t(*)[68])(dsm + 34816);
        uint32_t (*Ps)[68] = (uint32_t(*)[68])(dsm + 52224);
        const int warp = tid >> 5, lane = tid & 31;
        const int g = lane >> 2, tig = lane & 3;
        const int lr = tid >> 1, lc = (tid & 1) * 32;
        const int r0 = warp * 16;
        const float scl = (mode == 0) ? 0.125f : 8.0f;

        {   // Q tile -> smem (tf32)
            const float4* src = (const float4*)(g_q + ((size_t)bh * T_ + qt * 64 + lr) * HD_ + lc);
            #pragma unroll
            for (int i = 0; i < 8; i++) {
                float4 f = src[i];
                uint4 t2; t2.x = f2tf32(f.x); t2.y = f2tf32(f.y);
                t2.z = f2tf32(f.z); t2.w = f2tf32(f.w);
                *(uint4*)&Qs[lr][lc + 4*i] = t2;
            }
        }

        float m0 = -INFINITY, m1 = -INFINITY, l0 = 0.f, l1 = 0.f;
        float of[8][4];
        #pragma unroll
        for (int nf = 0; nf < 8; nf++)
            #pragma unroll
            for (int q = 0; q < 4; q++) of[nf][q] = 0.f;

        for (int kt = 0; kt <= qt; kt++) {
            __syncthreads();
            {   // K tile (row-major) + V tile (transposed), tf32
                const float4* ks = (const float4*)(g_k + ((size_t)bh * T_ + kt * 64 + lr) * HD_ + lc);
                const float4* vs = (const float4*)(g_v + ((size_t)bh * T_ + kt * 64 + lr) * HD_ + lc);
                #pragma unroll
                for (int i = 0; i < 8; i++) {
                    float4 f = ks[i];
                    uint4 t2; t2.x = f2tf32(f.x); t2.y = f2tf32(f.y);
                    t2.z = f2tf32(f.z); t2.w = f2tf32(f.w);
                    *(uint4*)&Ks[lr][lc + 4*i] = t2;
                    float4 v = vs[i];
                    Vt[lc + 4*i + 0][lr] = f2tf32(v.x);
                    Vt[lc + 4*i + 1][lr] = f2tf32(v.y);
                    Vt[lc + 4*i + 2][lr] = f2tf32(v.z);
                    Vt[lc + 4*i + 3][lr] = f2tf32(v.w);
                }
            }
            __syncthreads();

            // S = Q K^T  (warp's 16 rows x 64 cols)
            float sf[8][4];
            #pragma unroll
            for (int nf = 0; nf < 8; nf++)
                #pragma unroll
                for (int q = 0; q < 4; q++) sf[nf][q] = 0.f;
            #pragma unroll
            for (int k0 = 0; k0 < 8; k0++) {
                const int kb8 = k0 * 8;
                uint32_t a0 = Qs[r0 + g][kb8 + tig],     a1 = Qs[r0 + 8 + g][kb8 + tig];
                uint32_t a2 = Qs[r0 + g][kb8 + tig + 4], a3 = Qs[r0 + 8 + g][kb8 + tig + 4];
                #pragma unroll
                for (int nf = 0; nf < 8; nf++)
                    mma_tf32(sf[nf][0], sf[nf][1], sf[nf][2], sf[nf][3],
                             a0, a1, a2, a3,
                             Ks[nf*8 + g][kb8 + tig], Ks[nf*8 + g][kb8 + tig + 4]);
            }

            // scale + causal mask (diagonal tile only)
            const int rlo = r0 + g, rhi = rlo + 8;
            #pragma unroll
            for (int nf = 0; nf < 8; nf++) {
                const int c0c = nf * 8 + 2 * tig;
                sf[nf][0] *= scl; sf[nf][1] *= scl;
                sf[nf][2] *= scl; sf[nf][3] *= scl;
                if (kt == qt) {
                    if (c0c     > rlo) sf[nf][0] = -1e30f;
                    if (c0c + 1 > rlo) sf[nf][1] = -1e30f;
                    if (c0c     > rhi) sf[nf][2] = -1e30f;
                    if (c0c + 1 > rhi) sf[nf][3] = -1e30f;
                }
            }

            // online softmax (rows rlo, rhi)
            float mx0 = -INFINITY, mx1 = -INFINITY;
            #pragma unroll
            for (int nf = 0; nf < 8; nf++) {
                mx0 = fmaxf(mx0, fmaxf(sf[nf][0], sf[nf][1]));
                mx1 = fmaxf(mx1, fmaxf(sf[nf][2], sf[nf][3]));
            }
            mx0 = fmaxf(mx0, __shfl_xor_sync(0xffffffffu, mx0, 1));
            mx0 = fmaxf(mx0, __shfl_xor_sync(0xffffffffu, mx0, 2));
            mx1 = fmaxf(mx1, __shfl_xor_sync(0xffffffffu, mx1, 1));
            mx1 = fmaxf(mx1, __shfl_xor_sync(0xffffffffu, mx1, 2));
            const float mn0 = fmaxf(m0, mx0), mn1 = fmaxf(m1, mx1);
            const float cr0 = __expf(m0 - mn0), cr1 = __expf(m1 - mn1);

            float s0 = 0.f, s1 = 0.f;
            #pragma unroll
            for (int nf = 0; nf < 8; nf++) {
                float p0 = __expf(sf[nf][0] - mn0);
                float p1 = __expf(sf[nf][1] - mn0);
                float p2 = __expf(sf[nf][2] - mn1);
                float p3 = __expf(sf[nf][3] - mn1);
                s0 += p0 + p1; s1 += p2 + p3;
                const int cc = nf * 8 + 2 * tig;
                Ps[rlo][cc]     = f2tf32(p0);
                Ps[rlo][cc + 1] = f2tf32(p1);
                Ps[rhi][cc]     = f2tf32(p2);
                Ps[rhi][cc + 1] = f2tf32(p3);
                of[nf][0] *= cr0; of[nf][1] *= cr0;
                of[nf][2] *= cr1; of[nf][3] *= cr1;
            }
            s0 += __shfl_xor_sync(0xffffffffu, s0, 1);
            s0 += __shfl_xor_sync(0xffffffffu, s0, 2);
            s1 += __shfl_xor_sync(0xffffffffu, s1, 1);
            s1 += __shfl_xor_sync(0xffffffffu, s1, 2);
            l0 = l0 * cr0 + s0;
            l1 = l1 * cr1 + s1;
            m0 = mn0; m1 = mn1;
            __syncwarp();

            // O += P V   (A = P rows of this warp, B = V^T)
            #pragma unroll
            for (int k0 = 0; k0 < 8; k0++) {
                const int kb8 = k0 * 8;
                uint32_t a0 = Ps[r0 + g][kb8 + tig],     a1 = Ps[r0 + 8 + g][kb8 + tig];
                uint32_t a2 = Ps[r0 + g][kb8 + tig + 4], a3 = Ps[r0 + 8 + g][kb8 + tig + 4];
                #pragma unroll
                for (int nf = 0; nf < 8; nf++)
                    mma_tf32(of[nf][0], of[nf][1], of[nf][2], of[nf][3],
                             a0, a1, a2, a3,
                             Vt[nf*8 + g][kb8 + tig], Vt[nf*8 + g][kb8 + tig + 4]);
            }
            __syncwarp();
        }

        // write output rows
        const float il0 = 1.0f / l0, il1 = 1.0f / l1;
        const int rowg_lo = b * T_ + qt * 64 + r0 + g;
        const int rowg_hi = rowg_lo + 8;
        #pragma unroll
        for (int nf = 0; nf < 8; nf++) {
            const int col = h * HD_ + nf * 8 + 2 * tig;
            float2 vlo; vlo.x = of[nf][0] * il0; vlo.y = of[nf][1] * il0;
            float2 vhi; vhi.x = of[nf][2] * il1; vhi.y = of[nf][3] * il1;
            *(float2*)(g_y + (size_t)rowg_lo * C_ + col) = vlo;
            *(float2*)(g_y + (size_t)rowg_hi * C_ + col) = vhi;
        }
    } else {
        // ================= fp32 hyperbolic path, split-K halves =================
        float4* kb = (float4*)dsm;                      // [2][1024]
        float4* vb = (float4*)(dsm + 32768);            // [2][1024]
        float (*ssh)[17] = (float(*)[17])(dsm + 65536); // [128][17]
        float* tk2 = (float*)(dsm + 74240);             // [2][64]

        const int half = tid >> 6, stid = tid & 63;
        const int qi = qt * 64 + stid;

        float qreg[64];
        {
            const float4* qp = (const float4*)(g_q + ((size_t)bh * T_ + qi) * HD_);
            #pragma unroll
            for (int i = 0; i < 16; i++) {
                float4 f = qp[i];
                qreg[4*i] = f.x; qreg[4*i+1] = f.y; qreg[4*i+2] = f.z; qreg[4*i+3] = f.w;
            }
        }
        const float cu = curv[h - N1_];
        const float rcinv = sqrtf(1.0f / cu);
        const float my_tq = g_tq[(size_t)bh * T_ + qi];

        float m = -INFINITY, l = 0.0f;
        float o[64];
        #pragma unroll
        for (int d = 0; d < 64; d++) o[d] = 0.0f;

        const int nkt = qt + 1, steps = (nkt + 1) >> 1;
        for (int step = 0; step < steps; step++) {
            const int ktile = 2 * step + half;
            __syncthreads();
            if (ktile < nkt) {
                const float4* kg = (const float4*)(g_k + ((size_t)bh * T_ + ktile * 64) * HD_);
                const float4* vg = (const float4*)(g_v + ((size_t)bh * T_ + ktile * 64) * HD_);
                #pragma unroll
                for (int i = 0; i < 16; i++) {
                    kb[half * 1024 + stid + i * 64] = kg[stid + i * 64];
                    vb[half * 1024 + stid + i * 64] = vg[stid + i * 64];
                }
                tk2[half * 64 + stid] = g_tk[(size_t)bh * T_ + ktile * 64 + stid];
            }
            __syncthreads();
            if (ktile >= nkt) continue;

            const int nvalid = (ktile == qt) ? (stid + 1) : 64;
            for (int c0 = 0; c0 < 64; c0 += 16) {
                int jmax = nvalid - c0;
                if (jmax <= 0) break;
                if (jmax > 16) jmax = 16;

                float smax = -INFINITY;
                for (int j = 0; j < jmax; j++) {
                    const float4* kr = kb + half * 1024 + (c0 + j) * 16;
                    float d0 = 0.f, d1 = 0.f, d2 = 0.f, d3 = 0.f;
                    #pragma unroll
                    for (int d4 = 0; d4 < 16; d4++) {
                        float4 kk = kr[d4];
                        d0 = fmaf(qreg[4*d4+0], kk.x, d0);
                        d1 = fmaf(qreg[4*d4+1], kk.y, d1);
                        d2 = fmaf(qreg[4*d4+2], kk.z, d2);
                        d3 = fmaf(qreg[4*d4+3], kk.w, d3);
                    }
                    float dot = (d0 + d1) + (d2 + d3);
                    float am1 = fmaxf(cu * (my_tq * tk2[half * 64 + c0 + j] - dot) - 1.0f, 1e-7f);
                    float dis = rcinv * logf((am1 + 1.0f) + sqrtf(am1 * (am1 + 2.0f)));
                    float s = 1.0f / (1e-6f + dis);
                    ssh[tid][j] = s;
                    smax = fmaxf(smax, s);
                }

                float mnew = fmaxf(m, smax);
                float corr = __expf(m - mnew);
                l *= corr;
                #pragma unroll
                for (int d = 0; d < 64; d++) o[d] *= corr;

                for (int j = 0; j < jmax; j++) {
                    float p = __expf(ssh[tid][j] - mnew);
                    l += p;
                    const float4* vr = vb + half * 1024 + (c0 + j) * 16;
                    #pragma unroll
                    for (int d4 = 0; d4 < 16; d4++) {
                        float4 vv = vr[d4];
                        o[4*d4+0] = fmaf(p, vv.x, o[4*d4+0]);
                        o[4*d4+1] = fmaf(p, vv.y, o[4*d4+1]);
                        o[4*d4+2] = fmaf(p, vv.z, o[4*d4+2]);
                        o[4*d4+3] = fmaf(p, vv.w, o[4*d4+3]);
                    }
                }
                m = mnew;
            }
        }

        // merge halves
        __syncthreads();
        float* obuf = (float*)dsm;              // [64][68]
        float* msh  = (float*)(dsm + 32768);    // [64]
        float* lsh  = (float*)(dsm + 32768 + 256);
        if (half == 1) {
            msh[stid] = m; lsh[stid] = l;
            #pragma unroll
            for (int d = 0; d < 64; d += 4) {
                float4 v; v.x = o[d]; v.y = o[d+1]; v.z = o[d+2]; v.w = o[d+3];
                *(float4*)&obuf[stid * 68 + d] = v;
            }
        }
        __syncthreads();
        if (half == 0) {
            float mB = msh[stid], lB = lsh[stid];
            float mS = fmaxf(m, mB);
            float cA = __expf(m - mS), cB = __expf(mB - mS);
            float inv = 1.0f / (l * cA + lB * cB);
            float4* yp = (float4*)(g_y + (size_t)(b * T_ + qi) * C_ + h * HD_);
            #pragma unroll
            for (int i = 0; i < 16; i++) {
                float4 ov = *(float4*)&obuf[stid * 68 + 4*i];
                float4 r;
                r.x = (o[4*i+0] * cA + ov.x * cB) * inv;
                r.y = (o[4*i+1] * cA + ov.y * cB) * inv;
                r.z = (o[4*i+2] * cA + ov.z * cB) * inv;
                r.w = (o[4*i+3] * cA + ov.w * cB) * inv;
                yp[i] = r;
            }
        }
    }
}

// ---------------- launch ----------------
extern "C" void kernel_launch(void* const* d_in, const int* in_sizes, int n_in,
                              void* d_out, int out_size)
{
    const float* x      = (const float*)d_in[0];
    const float* qkv_w  = (const float*)d_in[1];
    const float* proj_w = (const float*)d_in[2];
    const float* proj_b = (const float*)d_in[3];
    const float* curv   = (const float*)d_in[4];
    float* out = (float*)d_out;

    void *pqkv = nullptr, *py = nullptr;
    cudaGetSymbolAddress(&pqkv, g_qkv);
    cudaGetSymbolAddress(&py, g_y);

    cudaFuncSetAttribute(flash_fused,
                         cudaFuncAttributeMaxDynamicSharedMemorySize, FSM_BYTES);

    // 1) qkv = x @ qkv_w^T
    mma_gemm<false><<<dim3(3 * C_ / 128, M_ / 128), 256>>>(
        x, qkv_w, nullptr, (float*)pqkv, M_, 3 * C_, C_);

    // 2) rotary + split + normalize/tq-tk
    rotary_kernel<<<(B_ * H_ * T_) / 8, 256>>>((const float*)pqkv, curv);

    // 3) fused attention (tensor path + fp32 hyperbolic path)
    flash_fused<<<dim3(T_ / 64, B_ * H_), 128, FSM_BYTES>>>(curv);

    // 4) out = y @ proj_w^T + proj_b
    mma_gemm<true><<<dim3(C_ / 128, M_ / 128), 256>>>(
        (const float*)py, proj_w, proj_b, out, M_, C_, C_);
}

// round 5
// speedup vs baseline: 2.7777x; 1.4207x over previous
#include <cuda_runtime.h>
#include <math.h>
#include <stdint.h>

#define B_  2
#define T_  2048
#define C_  1024
#define H_  16
#define HD_ 64
#define N1_ 6
#define N2_ 4
#define M_  (B_*T_)   // 4096

// ---------------- scratch (no allocation allowed) ----------------
__device__ float g_qkv[(size_t)M_ * 3 * C_];
__device__ float g_q[(size_t)B_ * H_ * T_ * HD_];
__device__ float g_k[(size_t)B_ * H_ * T_ * HD_];
__device__ float g_v[(size_t)B_ * H_ * T_ * HD_];
__device__ float g_tq[(size_t)B_ * H_ * T_];
__device__ float g_tk[(size_t)B_ * H_ * T_];
__device__ float g_y[(size_t)M_ * C_];

// ---------------- tf32 helpers ----------------
__device__ __forceinline__ uint32_t f2tf32(float f) {
    uint32_t u;
    asm("cvt.rna.tf32.f32 %0, %1;" : "=r"(u) : "f"(f));
    return u;
}
__device__ __forceinline__ void mma_tf32(float& c0, float& c1, float& c2, float& c3,
                                         uint32_t a0, uint32_t a1, uint32_t a2, uint32_t a3,
                                         uint32_t b0, uint32_t b1) {
    asm volatile(
        "mma.sync.aligned.m16n8k8.row.col.f32.tf32.tf32.f32 "
        "{%0,%1,%2,%3}, {%4,%5,%6,%7}, {%8,%9}, {%0,%1,%2,%3};"
        : "+f"(c0), "+f"(c1), "+f"(c2), "+f"(c3)
        : "r"(a0), "r"(a1), "r"(a2), "r"(a3), "r"(b0), "r"(b1));
}

// ================= tf32 mma.sync GEMM (passing R3/R4 version) ====
#define SPAD 36
template<bool BIAS>
__global__ __launch_bounds__(256) void mma_gemm(
    const float* __restrict__ A, const float* __restrict__ Bm,
    const float* __restrict__ bias, float* __restrict__ Cm,
    int M, int N, int K)
{
    __shared__ uint32_t As[128][SPAD];
    __shared__ uint32_t Bs[128][SPAD];

    const int tid = threadIdx.x;
    const int wid = tid >> 5, lane = tid & 31;
    const int g = lane >> 2, tig = lane & 3;
    const int warp_m = wid >> 2, warp_n = wid & 3;
    const int bm = blockIdx.y * 128, bn = blockIdx.x * 128;

    const int r  = tid >> 1;
    const int cq = (tid & 1) * 16;
    const float* Ap = A + (size_t)(bm + r) * K + cq;
    const float* Bp = Bm + (size_t)(bn + r) * K + cq;

    float acc[4][4][4];
    #pragma unroll
    for (int i = 0; i < 4; i++)
        #pragma unroll
        for (int j = 0; j < 4; j++)
            #pragma unroll
            for (int q = 0; q < 4; q++) acc[i][j][q] = 0.0f;

    const int nk = K >> 5;
    float4 ar[4], br[4];
    #pragma unroll
    for (int j = 0; j < 4; j++) {
        ar[j] = *(const float4*)(Ap + 4 * j);
        br[j] = *(const float4*)(Bp + 4 * j);
    }

    for (int i = 0; i < nk; i++) {
        __syncthreads();
        #pragma unroll
        for (int j = 0; j < 4; j++) {
            As[r][cq + 4*j + 0] = f2tf32(ar[j].x);
            As[r][cq + 4*j + 1] = f2tf32(ar[j].y);
            As[r][cq + 4*j + 2] = f2tf32(ar[j].z);
            As[r][cq + 4*j + 3] = f2tf32(ar[j].w);
            Bs[r][cq + 4*j + 0] = f2tf32(br[j].x);
            Bs[r][cq + 4*j + 1] = f2tf32(br[j].y);
            Bs[r][cq + 4*j + 2] = f2tf32(br[j].z);
            Bs[r][cq + 4*j + 3] = f2tf32(br[j].w);
        }
        __syncthreads();

        if (i + 1 < nk) {
            const int koff = (i + 1) * 32;
            #pragma unroll
            for (int j = 0; j < 4; j++) {
                ar[j] = *(const float4*)(Ap + koff + 4 * j);
                br[j] = *(const float4*)(Bp + koff + 4 * j);
            }
        }

        #pragma unroll
        for (int kk = 0; kk < 4; kk++) {
            const int k0 = kk * 8;
            uint32_t afr[4][4], bfr[4][2];
            #pragma unroll
            for (int mf = 0; mf < 4; mf++) {
                const int rowb = warp_m * 64 + mf * 16;
                afr[mf][0] = As[rowb + g    ][k0 + tig];
                afr[mf][1] = As[rowb + 8 + g][k0 + tig];
                afr[mf][2] = As[rowb + g    ][k0 + tig + 4];
                afr[mf][3] = As[rowb + 8 + g][k0 + tig + 4];
            }
            #pragma unroll
            for (int nf = 0; nf < 4; nf++) {
                const int colb = warp_n * 32 + nf * 8;
                bfr[nf][0] = Bs[colb + g][k0 + tig];
                bfr[nf][1] = Bs[colb + g][k0 + tig + 4];
            }
            #pragma unroll
            for (int mf = 0; mf < 4; mf++)
                #pragma unroll
                for (int nf = 0; nf < 4; nf++)
                    mma_tf32(acc[mf][nf][0], acc[mf][nf][1], acc[mf][nf][2], acc[mf][nf][3],
                             afr[mf][0], afr[mf][1], afr[mf][2], afr[mf][3],
                             bfr[nf][0], bfr[nf][1]);
        }
    }

    #pragma unroll
    for (int mf = 0; mf < 4; mf++) {
        const int row0 = bm + warp_m * 64 + mf * 16 + g;
        #pragma unroll
        for (int nf = 0; nf < 4; nf++) {
            const int col = bn + warp_n * 32 + nf * 8 + tig * 2;
            float b0 = 0.f, b1 = 0.f;
            if (BIAS) { b0 = bias[col]; b1 = bias[col + 1]; }
            float2 v0, v1;
            v0.x = acc[mf][nf][0] + b0; v0.y = acc[mf][nf][1] + b1;
            v1.x = acc[mf][nf][2] + b0; v1.y = acc[mf][nf][3] + b1;
            *(float2*)(Cm + (size_t)row0 * N + col)       = v0;
            *(float2*)(Cm + (size_t)(row0 + 8) * N + col) = v1;
        }
    }
}

// ---------------- rotary + split + per-head-group preprocessing ----------------
__global__ __launch_bounds__(256) void rotary_kernel(
    const float* __restrict__ qkv, const float* __restrict__ curv)
{
    const int warp = threadIdx.x >> 5, lane = threadIdx.x & 31;
    const int row = blockIdx.x * 8 + warp;
    const int t = row % T_;
    const int h = (row / T_) % H_;
    const int b = row / (T_ * H_);

    const float* src = qkv + (size_t)(b * T_ + t) * (3 * C_) + h * HD_ + lane;
    float q0 = src[0],        q1 = src[32];
    float k0 = src[C_],       k1 = src[C_ + 32];
    float v0 = src[2 * C_],   v1 = src[2 * C_ + 32];

    const float LOG2_1E4 = 13.287712379549449f;
    float inv_freq = exp2f(-(float)lane * (LOG2_1E4 / 32.0f));
    float fr = (float)t * inv_freq;
    float sn, cs;
    sincosf(fr, &sn, &cs);

    float qa = fmaf(q0, cs,  q1 * sn);
    float qb = fmaf(q1, cs, -q0 * sn);
    float ka = fmaf(k0, cs,  k1 * sn);
    float kb = fmaf(k1, cs, -k0 * sn);

    float sq = qa*qa + qb*qb;
    float sk = ka*ka + kb*kb;
    #pragma unroll
    for (int off = 16; off; off >>= 1) {
        sq += __shfl_xor_sync(0xffffffffu, sq, off);
        sk += __shfl_xor_sync(0xffffffffu, sk, off);
    }

    if (h >= N1_ + N2_) {
        float nq = 1.0f / fmaxf(sqrtf(sq), 1e-12f);
        float nk = 1.0f / fmaxf(sqrtf(sk), 1e-12f);
        qa *= nq; qb *= nq; ka *= nk; kb *= nk;
    } else if (h >= N1_) {
        if (lane == 0) {
            float c = curv[h - N1_];
            g_tq[row] = sqrtf(1.0f / c + sq);
            g_tk[row] = sqrtf(1.0f / c + sk);
        }
    }

    const size_t o = (size_t)row * HD_ + lane;
    g_q[o] = qa; g_q[o + 32] = qb;
    g_k[o] = ka; g_k[o + 32] = kb;
    g_v[o] = v0; g_v[o + 32] = v1;
}

// ---------------- unified tensor-core flash (all 3 geometries) ----------------
// grid (T/64, B*H), 128 threads (4 warps x 16 query rows).
// smem: Ks[64][68] @0, Vt[64][68] @17408, Ps[64][68] @34816 (also Q staging),
//       tksh[64] @52224. Total 52480 bytes.
#define FSM_BYTES 52480

__global__ __launch_bounds__(128) void flash_tc(const float* __restrict__ curv)
{
    extern __shared__ char dsm[];
    uint32_t (*Ks)[68] = (uint32_t(*)[68])(dsm);
    uint32_t (*Vt)[68] = (uint32_t(*)[68])(dsm + 17408);
    uint32_t (*Ps)[68] = (uint32_t(*)[68])(dsm + 34816);
    float* tksh = (float*)(dsm + 52224);

    const int bh = blockIdx.y;
    const int qt = (int)gridDim.x - 1 - (int)blockIdx.x;   // heavy blocks first
    const int h = bh % H_, b = bh / H_;
    const int mode = (h < N1_) ? 0 : (h < N1_ + N2_ ? 1 : 2);
    const int tid = threadIdx.x;
    const int warp = tid >> 5, lane = tid & 31;
    const int g = lane >> 2, tig = lane & 3;
    const int lr = tid >> 1, lc = (tid & 1) * 32;
    const int r0 = warp * 16;
    const int rlo = r0 + g, rhi = rlo + 8;

    // ---- stage Q via Ps, preload fragments into registers ----
    {
        const float4* src = (const float4*)(g_q + ((size_t)bh * T_ + qt * 64 + lr) * HD_ + lc);
        #pragma unroll
        for (int i = 0; i < 8; i++) {
            float4 f = src[i];
            uint4 t2; t2.x = f2tf32(f.x); t2.y = f2tf32(f.y);
            t2.z = f2tf32(f.z); t2.w = f2tf32(f.w);
            *(uint4*)&Ps[lr][lc + 4*i] = t2;
        }
    }
    __syncthreads();
    uint32_t qf[8][4];
    #pragma unroll
    for (int k0 = 0; k0 < 8; k0++) {
        const int kb8 = k0 * 8;
        qf[k0][0] = Ps[rlo][kb8 + tig];
        qf[k0][1] = Ps[rhi][kb8 + tig];
        qf[k0][2] = Ps[rlo][kb8 + tig + 4];
        qf[k0][3] = Ps[rhi][kb8 + tig + 4];
    }
    __syncthreads();

    // mode constants
    const float scl = (mode == 0) ? 0.125f : 8.0f;
    float cu = 1.f, rcinv = 1.f, ctq0 = 0.f, ctq1 = 0.f;
    if (mode == 1) {
        cu = curv[h - N1_];
        rcinv = rsqrtf(cu);
        ctq0 = cu * g_tq[(size_t)bh * T_ + qt * 64 + rlo];
        ctq1 = cu * g_tq[(size_t)bh * T_ + qt * 64 + rhi];
    }

    float m0 = -INFINITY, m1 = -INFINITY, l0 = 0.f, l1 = 0.f;
    float of[8][4];
    #pragma unroll
    for (int nf = 0; nf < 8; nf++)
        #pragma unroll
        for (int q = 0; q < 4; q++) of[nf][q] = 0.f;

    for (int kt = 0; kt <= qt; kt++) {
        __syncthreads();
        {   // K tile (row-major) + V tile (transposed), tf32
            const float4* ks = (const float4*)(g_k + ((size_t)bh * T_ + kt * 64 + lr) * HD_ + lc);
            const float4* vs = (const float4*)(g_v + ((size_t)bh * T_ + kt * 64 + lr) * HD_ + lc);
            #pragma unroll
            for (int i = 0; i < 8; i++) {
                float4 f = ks[i];
                uint4 t2; t2.x = f2tf32(f.x); t2.y = f2tf32(f.y);
                t2.z = f2tf32(f.z); t2.w = f2tf32(f.w);
                *(uint4*)&Ks[lr][lc + 4*i] = t2;
                float4 v = vs[i];
                Vt[lc + 4*i + 0][lr] = f2tf32(v.x);
                Vt[lc + 4*i + 1][lr] = f2tf32(v.y);
                Vt[lc + 4*i + 2][lr] = f2tf32(v.z);
                Vt[lc + 4*i + 3][lr] = f2tf32(v.w);
            }
            if (mode == 1 && tid < 64)
                tksh[tid] = g_tk[(size_t)bh * T_ + kt * 64 + tid];
        }
        __syncthreads();

        // S = Q K^T
        float sf[8][4];
        #pragma unroll
        for (int nf = 0; nf < 8; nf++)
            #pragma unroll
            for (int q = 0; q < 4; q++) sf[nf][q] = 0.f;
        #pragma unroll
        for (int k0 = 0; k0 < 8; k0++) {
            const int kb8 = k0 * 8;
            #pragma unroll
            for (int nf = 0; nf < 8; nf++)
                mma_tf32(sf[nf][0], sf[nf][1], sf[nf][2], sf[nf][3],
                         qf[k0][0], qf[k0][1], qf[k0][2], qf[k0][3],
                         Ks[nf*8 + g][kb8 + tig], Ks[nf*8 + g][kb8 + tig + 4]);
        }

        // score transform
        if (mode != 1) {
            #pragma unroll
            for (int nf = 0; nf < 8; nf++) {
                sf[nf][0] *= scl; sf[nf][1] *= scl;
                sf[nf][2] *= scl; sf[nf][3] *= scl;
            }
        } else {
            #pragma unroll
            for (int nf = 0; nf < 8; nf++) {
                const int cc = nf * 8 + 2 * tig;
                const float tk0 = tksh[cc], tk1 = tksh[cc + 1];
                #pragma unroll
                for (int q = 0; q < 4; q++) {
                    const float tkv = (q & 1) ? tk1 : tk0;
                    const float ctq = (q & 2) ? ctq1 : ctq0;
                    float am1 = fmaf(-cu, sf[nf][q], fmaf(ctq, tkv, -1.0f));
                    am1 = fmaxf(am1, 1e-7f);
                    float x = am1 * (am1 + 2.0f);
                    float root = x * rsqrtf(x);
                    float dis = rcinv * __logf(am1 + 1.0f + root);
                    sf[nf][q] = __fdividef(1.0f, 1e-6f + dis);
                }
            }
        }

        // causal mask on diagonal tile
        if (kt == qt) {
            #pragma unroll
            for (int nf = 0; nf < 8; nf++) {
                const int cc = nf * 8 + 2 * tig;
                if (cc     > rlo) sf[nf][0] = -1e30f;
                if (cc + 1 > rlo) sf[nf][1] = -1e30f;
                if (cc     > rhi) sf[nf][2] = -1e30f;
                if (cc + 1 > rhi) sf[nf][3] = -1e30f;
            }
        }

        // online softmax (rows rlo, rhi)
        float mx0 = -INFINITY, mx1 = -INFINITY;
        #pragma unroll
        for (int nf = 0; nf < 8; nf++) {
            mx0 = fmaxf(mx0, fmaxf(sf[nf][0], sf[nf][1]));
            mx1 = fmaxf(mx1, fmaxf(sf[nf][2], sf[nf][3]));
        }
        mx0 = fmaxf(mx0, __shfl_xor_sync(0xffffffffu, mx0, 1));
        mx0 = fmaxf(mx0, __shfl_xor_sync(0xffffffffu, mx0, 2));
        mx1 = fmaxf(mx1, __shfl_xor_sync(0xffffffffu, mx1, 1));
        mx1 = fmaxf(mx1, __shfl_xor_sync(0xffffffffu, mx1, 2));
        const float mn0 = fmaxf(m0, mx0), mn1 = fmaxf(m1, mx1);
        const float cr0 = __expf(m0 - mn0), cr1 = __expf(m1 - mn1);

        float s0 = 0.f, s1 = 0.f;
        #pragma unroll
        for (int nf = 0; nf < 8; nf++) {
            float p0 = __expf(sf[nf][0] - mn0);
            float p1 = __expf(sf[nf][1] - mn0);
            float p2 = __expf(sf[nf][2] - mn1);
            float p3 = __expf(sf[nf][3] - mn1);
            s0 += p0 + p1; s1 += p2 + p3;
            const int cc = nf * 8 + 2 * tig;
            Ps[rlo][cc]     = f2tf32(p0);
            Ps[rlo][cc + 1] = f2tf32(p1);
            Ps[rhi][cc]     = f2tf32(p2);
            Ps[rhi][cc + 1] = f2tf32(p3);
            of[nf][0] *= cr0; of[nf][1] *= cr0;
            of[nf][2] *= cr1; of[nf][3] *= cr1;
        }
        s0 += __shfl_xor_sync(0xffffffffu, s0, 1);
        s0 += __shfl_xor_sync(0xffffffffu, s0, 2);
        s1 += __shfl_xor_sync(0xffffffffu, s1, 1);
        s1 += __shfl_xor_sync(0xffffffffu, s1, 2);
        l0 = l0 * cr0 + s0;
        l1 = l1 * cr1 + s1;
        m0 = mn0; m1 = mn1;
        __syncwarp();

        // O += P V
        #pragma unroll
        for (int k0 = 0; k0 < 8; k0++) {
            const int kb8 = k0 * 8;
            uint32_t a0 = Ps[rlo][kb8 + tig],     a1 = Ps[rhi][kb8 + tig];
            uint32_t a2 = Ps[rlo][kb8 + tig + 4], a3 = Ps[rhi][kb8 + tig + 4];
            #pragma unroll
            for (int nf = 0; nf < 8; nf++)
                mma_tf32(of[nf][0], of[nf][1], of[nf][2], of[nf][3],
                         a0, a1, a2, a3,
                         Vt[nf*8 + g][kb8 + tig], Vt[nf*8 + g][kb8 + tig + 4]);
        }
        __syncwarp();
    }

    // write output rows
    const float il0 = 1.0f / l0, il1 = 1.0f / l1;
    const int rowg_lo = b * T_ + qt * 64 + rlo;
    const int rowg_hi = rowg_lo + 8;
    #pragma unroll
    for (int nf = 0; nf < 8; nf++) {
        const int col = h * HD_ + nf * 8 + 2 * tig;
        float2 vlo; vlo.x = of[nf][0] * il0; vlo.y = of[nf][1] * il0;
        float2 vhi; vhi.x = of[nf][2] * il1; vhi.y = of[nf][3] * il1;
        *(float2*)(g_y + (size_t)rowg_lo * C_ + col) = vlo;
        *(float2*)(g_y + (size_t)rowg_hi * C_ + col) = vhi;
    }
}

// ---------------- launch ----------------
extern "C" void kernel_launch(void* const* d_in, const int* in_sizes, int n_in,
                              void* d_out, int out_size)
{
    const float* x      = (const float*)d_in[0];
    const float* qkv_w  = (const float*)d_in[1];
    const float* proj_w = (const float*)d_in[2];
    const float* proj_b = (const float*)d_in[3];
    const float* curv   = (const float*)d_in[4];
    float* out = (float*)d_out;

    void *pqkv = nullptr, *py = nullptr;
    cudaGetSymbolAddress(&pqkv, g_qkv);
    cudaGetSymbolAddress(&py, g_y);

    cudaFuncSetAttribute(flash_tc,
                         cudaFuncAttributeMaxDynamicSharedMemorySize, FSM_BYTES);

    // 1) qkv = x @ qkv_w^T
    mma_gemm<false><<<dim3(3 * C_ / 128, M_ / 128), 256>>>(
        x, qkv_w, nullptr, (float*)pqkv, M_, 3 * C_, C_);

    // 2) rotary + split + normalize/tq-tk
    rotary_kernel<<<(B_ * H_ * T_) / 8, 256>>>((const float*)pqkv, curv);

    // 3) unified tensor-core attention
    flash_tc<<<dim3(T_ / 64, B_ * H_), 128, FSM_BYTES>>>(curv);

    // 4) out = y @ proj_w^T + proj_b
    mma_gemm<true><<<dim3(C_ / 128, M_ / 128), 256>>>(
        (const float*)py, proj_w, proj_b, out, M_, C_, C_);
}

// round 6
// speedup vs baseline: 2.8712x; 1.0337x over previous
#include <cuda_runtime.h>
#include <math.h>
#include <stdint.h>

#define B_  2
#define T_  2048
#define C_  1024
#define H_  16
#define HD_ 64
#define N1_ 6
#define N2_ 4
#define M_  (B_*T_)   // 4096

// ---------------- scratch (no allocation allowed) ----------------
__device__ float g_qkv[(size_t)M_ * 3 * C_];
__device__ float g_q[(size_t)B_ * H_ * T_ * HD_];
__device__ float g_k[(size_t)B_ * H_ * T_ * HD_];
__device__ float g_v[(size_t)B_ * H_ * T_ * HD_];
__device__ float g_tq[(size_t)B_ * H_ * T_];
__device__ float g_tk[(size_t)B_ * H_ * T_];
__device__ float g_y[(size_t)M_ * C_];

// ---------------- tf32 helpers ----------------
__device__ __forceinline__ uint32_t f2tf32(float f) {
    uint32_t u;
    asm("cvt.rna.tf32.f32 %0, %1;" : "=r"(u) : "f"(f));
    return u;
}
__device__ __forceinline__ void mma_tf32(float& c0, float& c1, float& c2, float& c3,
                                         uint32_t a0, uint32_t a1, uint32_t a2, uint32_t a3,
                                         uint32_t b0, uint32_t b1) {
    asm volatile(
        "mma.sync.aligned.m16n8k8.row.col.f32.tf32.tf32.f32 "
        "{%0,%1,%2,%3}, {%4,%5,%6,%7}, {%8,%9}, {%0,%1,%2,%3};"
        : "+f"(c0), "+f"(c1), "+f"(c2), "+f"(c3)
        : "r"(a0), "r"(a1), "r"(a2), "r"(a3), "r"(b0), "r"(b1));
}
__device__ __forceinline__ uint32_t smem_u32(const void* p) {
    uint32_t a;
    asm("{ .reg .u64 tmp; cvta.to.shared.u64 tmp, %1; cvt.u32.u64 %0, tmp; }"
        : "=r"(a) : "l"(p));
    return a;
}
__device__ __forceinline__ void cp16(uint32_t dst, const void* src) {
    asm volatile("cp.async.cg.shared.global [%0], [%1], 16;"
                 :: "r"(dst), "l"(src) : "memory");
}

// ================= tf32 mma.sync GEMM with cp.async pipeline ====
// 128x128 CTA tile, 8 warps (2x4), warp 64x32, K chunk 32, 2-stage cp.async.
// Dyn smem: 2 stages x (As[128][36] + Bs[128][36]) fp32 = 73728 bytes.
#define SPAD   36
#define GSTG   9216   // floats per stage (2*128*36)
#define GBOFF  4608   // B offset within stage (floats)
#define GSM_BYTES (2 * GSTG * 4)

template<bool BIAS>
__global__ __launch_bounds__(256, 2) void mma_gemm(
    const float* __restrict__ A, const float* __restrict__ Bm,
    const float* __restrict__ bias, float* __restrict__ Cm,
    int M, int N, int K)
{
    extern __shared__ float gsm[];
    const uint32_t sbase = smem_u32(gsm);

    const int tid = threadIdx.x;
    const int wid = tid >> 5, lane = tid & 31;
    const int g = lane >> 2, tig = lane & 3;
    const int warp_m = wid >> 2, warp_n = wid & 3;
    const int bm = blockIdx.y * 128, bn = blockIdx.x * 128;

    const int r  = tid >> 1;
    const int cq = (tid & 1) * 16;
    const float* Ap = A + (size_t)(bm + r) * K + cq;
    const float* Bp = Bm + (size_t)(bn + r) * K + cq;
    const uint32_t sA = sbase + (uint32_t)(r * SPAD + cq) * 4;
    const uint32_t sB = sA + GBOFF * 4;

    float acc[4][4][4];
    #pragma unroll
    for (int i = 0; i < 4; i++)
        #pragma unroll
        for (int j = 0; j < 4; j++)
            #pragma unroll
            for (int q = 0; q < 4; q++) acc[i][j][q] = 0.0f;

    const int nk = K >> 5;   // >= 2 always here (K>=1024)

    // issue chunk c into stage s
    auto issue = [&](int c, int s) {
        const float* ag = Ap + c * 32;
        const float* bg = Bp + c * 32;
        const uint32_t off = (uint32_t)(s * GSTG) * 4;
        #pragma unroll
        for (int j = 0; j < 4; j++) {
            cp16(sA + off + j * 16, ag + 4 * j);
            cp16(sB + off + j * 16, bg + 4 * j);
        }
        asm volatile("cp.async.commit_group;" ::: "memory");
    };

    issue(0, 0);
    issue(1, 1);

    for (int i = 0; i < nk; i++) {
        if (i + 2 < nk) {
            asm volatile("cp.async.wait_group 1;" ::: "memory");
        } else {
            asm volatile("cp.async.wait_group 0;" ::: "memory");
        }
        __syncthreads();

        const float* As = gsm + (i & 1) * GSTG;
        const float* Bs = As + GBOFF;

        #pragma unroll
        for (int kk = 0; kk < 4; kk++) {
            const int k0 = kk * 8;
            uint32_t afr[4][4], bfr[4][2];
            #pragma unroll
            for (int mf = 0; mf < 4; mf++) {
                const int rowb = warp_m * 64 + mf * 16;
                afr[mf][0] = f2tf32(As[(rowb + g    ) * SPAD + k0 + tig]);
                afr[mf][1] = f2tf32(As[(rowb + 8 + g) * SPAD + k0 + tig]);
                afr[mf][2] = f2tf32(As[(rowb + g    ) * SPAD + k0 + tig + 4]);
                afr[mf][3] = f2tf32(As[(rowb + 8 + g) * SPAD + k0 + tig + 4]);
            }
            #pragma unroll
            for (int nf = 0; nf < 4; nf++) {
                const int colb = warp_n * 32 + nf * 8;
                bfr[nf][0] = f2tf32(Bs[(colb + g) * SPAD + k0 + tig]);
                bfr[nf][1] = f2tf32(Bs[(colb + g) * SPAD + k0 + tig + 4]);
            }
            #pragma unroll
            for (int mf = 0; mf < 4; mf++)
                #pragma unroll
                for (int nf = 0; nf < 4; nf++)
                    mma_tf32(acc[mf][nf][0], acc[mf][nf][1], acc[mf][nf][2], acc[mf][nf][3],
                             afr[mf][0], afr[mf][1], afr[mf][2], afr[mf][3],
                             bfr[nf][0], bfr[nf][1]);
        }
        __syncthreads();

        if (i + 2 < nk) issue(i + 2, i & 1);
    }

    #pragma unroll
    for (int mf = 0; mf < 4; mf++) {
        const int row0 = bm + warp_m * 64 + mf * 16 + g;
        #pragma unroll
        for (int nf = 0; nf < 4; nf++) {
            const int col = bn + warp_n * 32 + nf * 8 + tig * 2;
            float b0 = 0.f, b1 = 0.f;
            if (BIAS) { b0 = bias[col]; b1 = bias[col + 1]; }
            float2 v0, v1;
            v0.x = acc[mf][nf][0] + b0; v0.y = acc[mf][nf][1] + b1;
            v1.x = acc[mf][nf][2] + b0; v1.y = acc[mf][nf][3] + b1;
            *(float2*)(Cm + (size_t)row0 * N + col)       = v0;
            *(float2*)(Cm + (size_t)(row0 + 8) * N + col) = v1;
        }
    }
}

// ---------------- rotary + split + per-head-group preprocessing ----------------
__global__ __launch_bounds__(256) void rotary_kernel(
    const float* __restrict__ qkv, const float* __restrict__ curv)
{
    const int warp = threadIdx.x >> 5, lane = threadIdx.x & 31;
    const int row = blockIdx.x * 8 + warp;
    const int t = row % T_;
    const int h = (row / T_) % H_;
    const int b = row / (T_ * H_);

    const float* src = qkv + (size_t)(b * T_ + t) * (3 * C_) + h * HD_ + lane;
    float q0 = src[0],        q1 = src[32];
    float k0 = src[C_],       k1 = src[C_ + 32];
    float v0 = src[2 * C_],   v1 = src[2 * C_ + 32];

    const float LOG2_1E4 = 13.287712379549449f;
    float inv_freq = exp2f(-(float)lane * (LOG2_1E4 / 32.0f));
    float fr = (float)t * inv_freq;
    float sn, cs;
    sincosf(fr, &sn, &cs);

    float qa = fmaf(q0, cs,  q1 * sn);
    float qb = fmaf(q1, cs, -q0 * sn);
    float ka = fmaf(k0, cs,  k1 * sn);
    float kb = fmaf(k1, cs, -k0 * sn);

    float sq = qa*qa + qb*qb;
    float sk = ka*ka + kb*kb;
    #pragma unroll
    for (int off = 16; off; off >>= 1) {
        sq += __shfl_xor_sync(0xffffffffu, sq, off);
        sk += __shfl_xor_sync(0xffffffffu, sk, off);
    }

    if (h >= N1_ + N2_) {
        float nq = 1.0f / fmaxf(sqrtf(sq), 1e-12f);
        float nk = 1.0f / fmaxf(sqrtf(sk), 1e-12f);
        qa *= nq; qb *= nq; ka *= nk; kb *= nk;
    } else if (h >= N1_) {
        if (lane == 0) {
            float c = curv[h - N1_];
            g_tq[row] = sqrtf(1.0f / c + sq);
            g_tk[row] = sqrtf(1.0f / c + sk);
        }
    }

    const size_t o = (size_t)row * HD_ + lane;
    g_q[o] = qa; g_q[o + 32] = qb;
    g_k[o] = ka; g_k[o + 32] = kb;
    g_v[o] = v0; g_v[o + 32] = v1;
}

// ---------------- unified tensor-core flash (all 3 geometries) ----------------
// grid (T/64, B*H), 128 threads (4 warps x 16 query rows).
// smem: Ks[64][68] @0, Vt[64][68] @17408, Ps[64][68] @34816 (also Q staging),
//       tksh[64] @52224. Total 52480 bytes.
#define FSM_BYTES 52480

__global__ __launch_bounds__(128) void flash_tc(const float* __restrict__ curv)
{
    extern __shared__ char dsm[];
    uint32_t (*Ks)[68] = (uint32_t(*)[68])(dsm);
    uint32_t (*Vt)[68] = (uint32_t(*)[68])(dsm + 17408);
    uint32_t (*Ps)[68] = (uint32_t(*)[68])(dsm + 34816);
    float* tksh = (float*)(dsm + 52224);

    const int bh = blockIdx.y;
    const int qt = (int)gridDim.x - 1 - (int)blockIdx.x;   // heavy blocks first
    const int h = bh % H_, b = bh / H_;
    const int mode = (h < N1_) ? 0 : (h < N1_ + N2_ ? 1 : 2);
    const int tid = threadIdx.x;
    const int warp = tid >> 5, lane = tid & 31;
    const int g = lane >> 2, tig = lane & 3;
    const int lr = tid >> 1, lc = (tid & 1) * 32;
    const int r0 = warp * 16;
    const int rlo = r0 + g, rhi = rlo + 8;

    // ---- stage Q via Ps, preload fragments into registers ----
    {
        const float4* src = (const float4*)(g_q + ((size_t)bh * T_ + qt * 64 + lr) * HD_ + lc);
        #pragma unroll
        for (int i = 0; i < 8; i++) {
            float4 f = src[i];
            uint4 t2; t2.x = f2tf32(f.x); t2.y = f2tf32(f.y);
            t2.z = f2tf32(f.z); t2.w = f2tf32(f.w);
            *(uint4*)&Ps[lr][lc + 4*i] = t2;
        }
    }
    __syncthreads();
    uint32_t qf[8][4];
    #pragma unroll
    for (int k0 = 0; k0 < 8; k0++) {
        const int kb8 = k0 * 8;
        qf[k0][0] = Ps[rlo][kb8 + tig];
        qf[k0][1] = Ps[rhi][kb8 + tig];
        qf[k0][2] = Ps[rlo][kb8 + tig + 4];
        qf[k0][3] = Ps[rhi][kb8 + tig + 4];
    }
    __syncthreads();

    // mode constants
    const float scl = (mode == 0) ? 0.125f : 8.0f;
    float cu = 1.f, rcinv = 1.f, ctq0 = 0.f, ctq1 = 0.f;
    if (mode == 1) {
        cu = curv[h - N1_];
        rcinv = rsqrtf(cu);
        ctq0 = cu * g_tq[(size_t)bh * T_ + qt * 64 + rlo];
        ctq1 = cu * g_tq[(size_t)bh * T_ + qt * 64 + rhi];
    }

    float m0 = -INFINITY, m1 = -INFINITY, l0 = 0.f, l1 = 0.f;
    float of[8][4];
    #pragma unroll
    for (int nf = 0; nf < 8; nf++)
        #pragma unroll
        for (int q = 0; q < 4; q++) of[nf][q] = 0.f;

    for (int kt = 0; kt <= qt; kt++) {
        __syncthreads();
        {   // K tile (row-major) + V tile (transposed), tf32
            const float4* ks = (const float4*)(g_k + ((size_t)bh * T_ + kt * 64 + lr) * HD_ + lc);
            const float4* vs = (const float4*)(g_v + ((size_t)bh * T_ + kt * 64 + lr) * HD_ + lc);
            #pragma unroll
            for (int i = 0; i < 8; i++) {
                float4 f = ks[i];
                uint4 t2; t2.x = f2tf32(f.x); t2.y = f2tf32(f.y);
                t2.z = f2tf32(f.z); t2.w = f2tf32(f.w);
                *(uint4*)&Ks[lr][lc + 4*i] = t2;
                float4 v = vs[i];
                Vt[lc + 4*i + 0][lr] = f2tf32(v.x);
                Vt[lc + 4*i + 1][lr] = f2tf32(v.y);
                Vt[lc + 4*i + 2][lr] = f2tf32(v.z);
                Vt[lc + 4*i + 3][lr] = f2tf32(v.w);
            }
            if (mode == 1 && tid < 64)
                tksh[tid] = g_tk[(size_t)bh * T_ + kt * 64 + tid];
        }
        __syncthreads();

        // S = Q K^T
        float sf[8][4];
        #pragma unroll
        for (int nf = 0; nf < 8; nf++)
            #pragma unroll
            for (int q = 0; q < 4; q++) sf[nf][q] = 0.f;
        #pragma unroll
        for (int k0 = 0; k0 < 8; k0++) {
            const int kb8 = k0 * 8;
            #pragma unroll
            for (int nf = 0; nf < 8; nf++)
                mma_tf32(sf[nf][0], sf[nf][1], sf[nf][2], sf[nf][3],
                         qf[k0][0], qf[k0][1], qf[k0][2], qf[k0][3],
                         Ks[nf*8 + g][kb8 + tig], Ks[nf*8 + g][kb8 + tig + 4]);
        }

        // score transform
        if (mode != 1) {
            #pragma unroll
            for (int nf = 0; nf < 8; nf++) {
                sf[nf][0] *= scl; sf[nf][1] *= scl;
                sf[nf][2] *= scl; sf[nf][3] *= scl;
            }
        } else {
            #pragma unroll
            for (int nf = 0; nf < 8; nf++) {
                const int cc = nf * 8 + 2 * tig;
                const float tk0 = tksh[cc], tk1 = tksh[cc + 1];
                #pragma unroll
                for (int q = 0; q < 4; q++) {
                    const float tkv = (q & 1) ? tk1 : tk0;
                    const float ctq = (q & 2) ? ctq1 : ctq0;
                    float am1 = fmaf(-cu, sf[nf][q], fmaf(ctq, tkv, -1.0f));
                    am1 = fmaxf(am1, 1e-7f);
                    float x = am1 * (am1 + 2.0f);
                    float root = x * rsqrtf(x);
                    float dis = rcinv * __logf(am1 + 1.0f + root);
                    sf[nf][q] = __fdividef(1.0f, 1e-6f + dis);
                }
            }
        }

        // causal mask on diagonal tile
        if (kt == qt) {
            #pragma unroll
            for (int nf = 0; nf < 8; nf++) {
                const int cc = nf * 8 + 2 * tig;
                if (cc     > rlo) sf[nf][0] = -1e30f;
                if (cc + 1 > rlo) sf[nf][1] = -1e30f;
                if (cc     > rhi) sf[nf][2] = -1e30f;
                if (cc + 1 > rhi) sf[nf][3] = -1e30f;
            }
        }

        // online softmax (rows rlo, rhi)
        float mx0 = -INFINITY, mx1 = -INFINITY;
        #pragma unroll
        for (int nf = 0; nf < 8; nf++) {
            mx0 = fmaxf(mx0, fmaxf(sf[nf][0], sf[nf][1]));
            mx1 = fmaxf(mx1, fmaxf(sf[nf][2], sf[nf][3]));
        }
        mx0 = fmaxf(mx0, __shfl_xor_sync(0xffffffffu, mx0, 1));
        mx0 = fmaxf(mx0, __shfl_xor_sync(0xffffffffu, mx0, 2));
        mx1 = fmaxf(mx1, __shfl_xor_sync(0xffffffffu, mx1, 1));
        mx1 = fmaxf(mx1, __shfl_xor_sync(0xffffffffu, mx1, 2));
        const float mn0 = fmaxf(m0, mx0), mn1 = fmaxf(m1, mx1);
        const float cr0 = __expf(m0 - mn0), cr1 = __expf(m1 - mn1);

        float s0 = 0.f, s1 = 0.f;
        #pragma unroll
        for (int nf = 0; nf < 8; nf++) {
            float p0 = __expf(sf[nf][0] - mn0);
            float p1 = __expf(sf[nf][1] - mn0);
            float p2 = __expf(sf[nf][2] - mn1);
            float p3 = __expf(sf[nf][3] - mn1);
            s0 += p0 + p1; s1 += p2 + p3;
            const int cc = nf * 8 + 2 * tig;
            Ps[rlo][cc]     = f2tf32(p0);
            Ps[rlo][cc + 1] = f2tf32(p1);
            Ps[rhi][cc]     = f2tf32(p2);
            Ps[rhi][cc + 1] = f2tf32(p3);
            of[nf][0] *= cr0; of[nf][1] *= cr0;
            of[nf][2] *= cr1; of[nf][3] *= cr1;
        }
        s0 += __shfl_xor_sync(0xffffffffu, s0, 1);
        s0 += __shfl_xor_sync(0xffffffffu, s0, 2);
        s1 += __shfl_xor_sync(0xffffffffu, s1, 1);
        s1 += __shfl_xor_sync(0xffffffffu, s1, 2);
        l0 = l0 * cr0 + s0;
        l1 = l1 * cr1 + s1;
        m0 = mn0; m1 = mn1;
        __syncwarp();

        // O += P V
        #pragma unroll
        for (int k0 = 0; k0 < 8; k0++) {
            const int kb8 = k0 * 8;
            uint32_t a0 = Ps[rlo][kb8 + tig],     a1 = Ps[rhi][kb8 + tig];
            uint32_t a2 = Ps[rlo][kb8 + tig + 4], a3 = Ps[rhi][kb8 + tig + 4];
            #pragma unroll
            for (int nf = 0; nf < 8; nf++)
                mma_tf32(of[nf][0], of[nf][1], of[nf][2], of[nf][3],
                         a0, a1, a2, a3,
                         Vt[nf*8 + g][kb8 + tig], Vt[nf*8 + g][kb8 + tig + 4]);
        }
        __syncwarp();
    }

    // write output rows
    const float il0 = 1.0f / l0, il1 = 1.0f / l1;
    const int rowg_lo = b * T_ + qt * 64 + rlo;
    const int rowg_hi = rowg_lo + 8;
    #pragma unroll
    for (int nf = 0; nf < 8; nf++) {
        const int col = h * HD_ + nf * 8 + 2 * tig;
        float2 vlo; vlo.x = of[nf][0] * il0; vlo.y = of[nf][1] * il0;
        float2 vhi; vhi.x = of[nf][2] * il1; vhi.y = of[nf][3] * il1;
        *(float2*)(g_y + (size_t)rowg_lo * C_ + col) = vlo;
        *(float2*)(g_y + (size_t)rowg_hi * C_ + col) = vhi;
    }
}

// ---------------- launch ----------------
extern "C" void kernel_launch(void* const* d_in, const int* in_sizes, int n_in,
                              void* d_out, int out_size)
{
    const float* x      = (const float*)d_in[0];
    const float* qkv_w  = (const float*)d_in[1];
    const float* proj_w = (const float*)d_in[2];
    const float* proj_b = (const float*)d_in[3];
    const float* curv   = (const float*)d_in[4];
    float* out = (float*)d_out;

    void *pqkv = nullptr, *py = nullptr;
    cudaGetSymbolAddress(&pqkv, g_qkv);
    cudaGetSymbolAddress(&py, g_y);

    cudaFuncSetAttribute(flash_tc,
                         cudaFuncAttributeMaxDynamicSharedMemorySize, FSM_BYTES);
    cudaFuncSetAttribute(mma_gemm<false>,
                         cudaFuncAttributeMaxDynamicSharedMemorySize, GSM_BYTES);
    cudaFuncSetAttribute(mma_gemm<true>,
                         cudaFuncAttributeMaxDynamicSharedMemorySize, GSM_BYTES);

    // 1) qkv = x @ qkv_w^T
    mma_gemm<false><<<dim3(3 * C_ / 128, M_ / 128), 256, GSM_BYTES>>>(
        x, qkv_w, nullptr, (float*)pqkv, M_, 3 * C_, C_);

    // 2) rotary + split + normalize/tq-tk
    rotary_kernel<<<(B_ * H_ * T_) / 8, 256>>>((const float*)pqkv, curv);

    // 3) unified tensor-core attention
    flash_tc<<<dim3(T_ / 64, B_ * H_), 128, FSM_BYTES>>>(curv);

    // 4) out = y @ proj_w^T + proj_b
    mma_gemm<true><<<dim3(C_ / 128, M_ / 128), 256, GSM_BYTES>>>(
        (const float*)py, proj_w, proj_b, out, M_, C_, C_);
}

// round 7
// speedup vs baseline: 2.9795x; 1.0377x over previous
#include <cuda_runtime.h>
#include <math.h>
#include <stdint.h>

#define B_  2
#define T_  2048
#define C_  1024
#define H_  16
#define HD_ 64
#define N1_ 6
#define N2_ 4
#define M_  (B_*T_)   // 4096

// ---------------- scratch (no allocation allowed) ----------------
__device__ float g_qkv[(size_t)M_ * 3 * C_];
__device__ float g_q[(size_t)B_ * H_ * T_ * HD_];
__device__ float g_k[(size_t)B_ * H_ * T_ * HD_];
__device__ float g_v[(size_t)B_ * H_ * T_ * HD_];
__device__ float g_tq[(size_t)B_ * H_ * T_];
__device__ float g_tk[(size_t)B_ * H_ * T_];
__device__ float g_y[(size_t)M_ * C_];

// ---------------- tf32 helpers ----------------
__device__ __forceinline__ uint32_t f2tf32(float f) {
    uint32_t u;
    asm("cvt.rna.tf32.f32 %0, %1;" : "=r"(u) : "f"(f));
    return u;
}
__device__ __forceinline__ void mma_tf32(float& c0, float& c1, float& c2, float& c3,
                                         uint32_t a0, uint32_t a1, uint32_t a2, uint32_t a3,
                                         uint32_t b0, uint32_t b1) {
    asm volatile(
        "mma.sync.aligned.m16n8k8.row.col.f32.tf32.tf32.f32 "
        "{%0,%1,%2,%3}, {%4,%5,%6,%7}, {%8,%9}, {%0,%1,%2,%3};"
        : "+f"(c0), "+f"(c1), "+f"(c2), "+f"(c3)
        : "r"(a0), "r"(a1), "r"(a2), "r"(a3), "r"(b0), "r"(b1));
}
__device__ __forceinline__ uint32_t smem_u32(const void* p) {
    uint32_t a;
    asm("{ .reg .u64 tmp; cvta.to.shared.u64 tmp, %1; cvt.u32.u64 %0, tmp; }"
        : "=r"(a) : "l"(p));
    return a;
}
__device__ __forceinline__ void cp16(uint32_t dst, const void* src) {
    asm volatile("cp.async.cg.shared.global [%0], [%1], 16;"
                 :: "r"(dst), "l"(src) : "memory");
}

// ================= tf32 mma.sync GEMM, 3-stage cp.async, 1 sync/chunk ====
// 128x128 CTA tile, 8 warps (2x4), warp 64x32, K chunk 32.
#define SPAD   36
#define GSTG   9216   // floats per stage (2*128*36)
#define GBOFF  4608   // B offset within stage (floats)
#define GSM_BYTES (3 * GSTG * 4)

template<bool BIAS>
__global__ __launch_bounds__(256, 2) void mma_gemm(
    const float* __restrict__ A, const float* __restrict__ Bm,
    const float* __restrict__ bias, float* __restrict__ Cm,
    int M, int N, int K)
{
    extern __shared__ float gsm[];
    const uint32_t sbase = smem_u32(gsm);

    const int tid = threadIdx.x;
    const int wid = tid >> 5, lane = tid & 31;
    const int g = lane >> 2, tig = lane & 3;
    const int warp_m = wid >> 2, warp_n = wid & 3;
    const int bm = blockIdx.y * 128, bn = blockIdx.x * 128;

    const int r  = tid >> 1;
    const int cq = (tid & 1) * 16;
    const float* Ap = A + (size_t)(bm + r) * K + cq;
    const float* Bp = Bm + (size_t)(bn + r) * K + cq;
    const uint32_t sA = sbase + (uint32_t)(r * SPAD + cq) * 4;
    const uint32_t sB = sA + GBOFF * 4;

    float acc[4][4][4];
    #pragma unroll
    for (int i = 0; i < 4; i++)
        #pragma unroll
        for (int j = 0; j < 4; j++)
            #pragma unroll
            for (int q = 0; q < 4; q++) acc[i][j][q] = 0.0f;

    const int nk = K >> 5;   // 32 here

    auto issue = [&](int c, int s) {
        const float* ag = Ap + c * 32;
        const float* bg = Bp + c * 32;
        const uint32_t off = (uint32_t)(s * GSTG) * 4;
        #pragma unroll
        for (int j = 0; j < 4; j++) {
            cp16(sA + off + j * 16, ag + 4 * j);
            cp16(sB + off + j * 16, bg + 4 * j);
        }
        asm volatile("cp.async.commit_group;" ::: "memory");
    };

    issue(0, 0);
    issue(1, 1);

    for (int i = 0; i < nk; i++) {
        if (i + 2 < nk) {
            asm volatile("cp.async.wait_group 1;" ::: "memory");
        } else {
            asm volatile("cp.async.wait_group 0;" ::: "memory");
        }
        __syncthreads();

        if (i + 2 < nk) issue(i + 2, (i + 2) % 3);

        const float* As = gsm + (i % 3) * GSTG;
        const float* Bs = As + GBOFF;

        #pragma unroll
        for (int kk = 0; kk < 4; kk++) {
            const int k0 = kk * 8;
            uint32_t afr[4][4], bfr[4][2];
            #pragma unroll
            for (int mf = 0; mf < 4; mf++) {
                const int rowb = warp_m * 64 + mf * 16;
                afr[mf][0] = f2tf32(As[(rowb + g    ) * SPAD + k0 + tig]);
                afr[mf][1] = f2tf32(As[(rowb + 8 + g) * SPAD + k0 + tig]);
                afr[mf][2] = f2tf32(As[(rowb + g    ) * SPAD + k0 + tig + 4]);
                afr[mf][3] = f2tf32(As[(rowb + 8 + g) * SPAD + k0 + tig + 4]);
            }
            #pragma unroll
            for (int nf = 0; nf < 4; nf++) {
                const int colb = warp_n * 32 + nf * 8;
                bfr[nf][0] = f2tf32(Bs[(colb + g) * SPAD + k0 + tig]);
                bfr[nf][1] = f2tf32(Bs[(colb + g) * SPAD + k0 + tig + 4]);
            }
            #pragma unroll
            for (int mf = 0; mf < 4; mf++)
                #pragma unroll
                for (int nf = 0; nf < 4; nf++)
                    mma_tf32(acc[mf][nf][0], acc[mf][nf][1], acc[mf][nf][2], acc[mf][nf][3],
                             afr[mf][0], afr[mf][1], afr[mf][2], afr[mf][3],
                             bfr[nf][0], bfr[nf][1]);
        }
    }

    #pragma unroll
    for (int mf = 0; mf < 4; mf++) {
        const int row0 = bm + warp_m * 64 + mf * 16 + g;
        #pragma unroll
        for (int nf = 0; nf < 4; nf++) {
            const int col = bn + warp_n * 32 + nf * 8 + tig * 2;
            float b0 = 0.f, b1 = 0.f;
            if (BIAS) { b0 = bias[col]; b1 = bias[col + 1]; }
            float2 v0, v1;
            v0.x = acc[mf][nf][0] + b0; v0.y = acc[mf][nf][1] + b1;
            v1.x = acc[mf][nf][2] + b0; v1.y = acc[mf][nf][3] + b1;
            *(float2*)(Cm + (size_t)row0 * N + col)       = v0;
            *(float2*)(Cm + (size_t)(row0 + 8) * N + col) = v1;
        }
    }
}

// ---------------- rotary + split + per-head-group preprocessing ----------------
__global__ __launch_bounds__(256) void rotary_kernel(
    const float* __restrict__ qkv, const float* __restrict__ curv)
{
    const int warp = threadIdx.x >> 5, lane = threadIdx.x & 31;
    const int row = blockIdx.x * 8 + warp;
    const int t = row % T_;
    const int h = (row / T_) % H_;
    const int b = row / (T_ * H_);

    const float* src = qkv + (size_t)(b * T_ + t) * (3 * C_) + h * HD_ + lane;
    float q0 = src[0],        q1 = src[32];
    float k0 = src[C_],       k1 = src[C_ + 32];
    float v0 = src[2 * C_],   v1 = src[2 * C_ + 32];

    const float LOG2_1E4 = 13.287712379549449f;
    float inv_freq = exp2f(-(float)lane * (LOG2_1E4 / 32.0f));
    float fr = (float)t * inv_freq;
    float sn, cs;
    sincosf(fr, &sn, &cs);

    float qa = fmaf(q0, cs,  q1 * sn);
    float qb = fmaf(q1, cs, -q0 * sn);
    float ka = fmaf(k0, cs,  k1 * sn);
    float kb = fmaf(k1, cs, -k0 * sn);

    float sq = qa*qa + qb*qb;
    float sk = ka*ka + kb*kb;
    #pragma unroll
    for (int off = 16; off; off >>= 1) {
        sq += __shfl_xor_sync(0xffffffffu, sq, off);
        sk += __shfl_xor_sync(0xffffffffu, sk, off);
    }

    if (h >= N1_ + N2_) {
        float nq = 1.0f / fmaxf(sqrtf(sq), 1e-12f);
        float nk = 1.0f / fmaxf(sqrtf(sk), 1e-12f);
        qa *= nq; qb *= nq; ka *= nk; kb *= nk;
    } else if (h >= N1_) {
        if (lane == 0) {
            float c = curv[h - N1_];
            g_tq[row] = sqrtf(1.0f / c + sq);
            g_tk[row] = sqrtf(1.0f / c + sk);
        }
    }

    const size_t o = (size_t)row * HD_ + lane;
    g_q[o] = qa; g_q[o + 32] = qb;
    g_k[o] = ka; g_k[o + 32] = kb;
    g_v[o] = v0; g_v[o + 32] = v1;
}

// ---------------- unified tensor-core flash, cp.async double-buffered ----------
// grid (T/64, B*H), 128 threads (4 warps x 16 query rows).
// smem bytes: Kst 2x64x68x4 @0 (stage 17408), Vst 2x64x72x4 @34816 (stage 18432),
//             Ps[64][68] u32 @71680, tksh 2x64 f @89088. Total 89600.
#define FK_STG 17408
#define FV_OFF 34816
#define FV_STG 18432
#define FP_OFF 71680
#define FT_OFF 89088
#define FSM_BYTES 89600

__global__ __launch_bounds__(128) void flash_tc(const float* __restrict__ curv)
{
    extern __shared__ char dsm[];
    const uint32_t sb = smem_u32(dsm);
    uint32_t (*Ps)[68] = (uint32_t(*)[68])(dsm + FP_OFF);

    const int bh = blockIdx.y;
    const int qt = (int)gridDim.x - 1 - (int)blockIdx.x;   // heavy blocks first
    const int h = bh % H_, b = bh / H_;
    const int mode = (h < N1_) ? 0 : (h < N1_ + N2_ ? 1 : 2);
    const int tid = threadIdx.x;
    const int warp = tid >> 5, lane = tid & 31;
    const int g = lane >> 2, tig = lane & 3;
    const int lr = tid >> 1, lc = (tid & 1) * 32;
    const int r0 = warp * 16;
    const int rlo = r0 + g, rhi = rlo + 8;

    // issue K/V (+tk) tile c into stage st
    auto issue = [&](int c, int st) {
        if (c <= qt) {
            const float* ksrc = g_k + ((size_t)bh * T_ + c * 64 + lr) * HD_ + lc;
            const float* vsrc = g_v + ((size_t)bh * T_ + c * 64 + lr) * HD_ + lc;
            const uint32_t kdst = sb + st * FK_STG + lr * 272 + (tid & 1) * 128;
            const uint32_t vdst = sb + FV_OFF + st * FV_STG + lr * 288 + (tid & 1) * 128;
            #pragma unroll
            for (int j = 0; j < 8; j++) {
                cp16(kdst + j * 16, ksrc + j * 4);
                cp16(vdst + j * 16, vsrc + j * 4);
            }
            if (mode == 1 && tid < 16)
                cp16(sb + FT_OFF + st * 256 + tid * 16,
                     g_tk + (size_t)bh * T_ + c * 64 + tid * 4);
        }
        asm volatile("cp.async.commit_group;" ::: "memory");
    };

    issue(0, 0);

    // ---- stage Q via Ps, preload fragments into registers ----
    {
        const float4* src = (const float4*)(g_q + ((size_t)bh * T_ + qt * 64 + lr) * HD_ + lc);
        #pragma unroll
        for (int i = 0; i < 8; i++) {
            float4 f = src[i];
            uint4 t2; t2.x = f2tf32(f.x); t2.y = f2tf32(f.y);
            t2.z = f2tf32(f.z); t2.w = f2tf32(f.w);
            *(uint4*)&Ps[lr][lc + 4*i] = t2;
        }
    }
    __syncthreads();
    uint32_t qf[8][4];
    #pragma unroll
    for (int k0 = 0; k0 < 8; k0++) {
        const int kb8 = k0 * 8;
        qf[k0][0] = Ps[rlo][kb8 + tig];
        qf[k0][1] = Ps[rhi][kb8 + tig];
        qf[k0][2] = Ps[rlo][kb8 + tig + 4];
        qf[k0][3] = Ps[rhi][kb8 + tig + 4];
    }
    __syncthreads();

    // mode constants
    const float scl = (mode == 0) ? 0.125f : 8.0f;
    float cu = 1.f, rcinv = 1.f, ctq0 = 0.f, ctq1 = 0.f;
    if (mode == 1) {
        cu = curv[h - N1_];
        rcinv = rsqrtf(cu);
        ctq0 = cu * g_tq[(size_t)bh * T_ + qt * 64 + rlo];
        ctq1 = cu * g_tq[(size_t)bh * T_ + qt * 64 + rhi];
    }

    float m0 = -INFINITY, m1 = -INFINITY, l0 = 0.f, l1 = 0.f;
    float of[8][4];
    #pragma unroll
    for (int nf = 0; nf < 8; nf++)
        #pragma unroll
        for (int q = 0; q < 4; q++) of[nf][q] = 0.f;

    for (int kt = 0; kt <= qt; kt++) {
        const int st = kt & 1;
        issue(kt + 1, st ^ 1);
        if (kt + 1 <= qt) {
            asm volatile("cp.async.wait_group 1;" ::: "memory");
        } else {
            asm volatile("cp.async.wait_group 0;" ::: "memory");
        }
        __syncthreads();

        const float* Kst = (const float*)(dsm + st * FK_STG);
        const float* Vst = (const float*)(dsm + FV_OFF + st * FV_STG);
        const float* tks = (const float*)(dsm + FT_OFF + st * 256);

        // S = Q K^T
        float sf[8][4];
        #pragma unroll
        for (int nf = 0; nf < 8; nf++)
            #pragma unroll
            for (int q = 0; q < 4; q++) sf[nf][q] = 0.f;
        #pragma unroll
        for (int k0 = 0; k0 < 8; k0++) {
            const int kb8 = k0 * 8;
            #pragma unroll
            for (int nf = 0; nf < 8; nf++) {
                uint32_t b0 = f2tf32(Kst[(nf*8 + g) * 68 + kb8 + tig]);
                uint32_t b1 = f2tf32(Kst[(nf*8 + g) * 68 + kb8 + tig + 4]);
                mma_tf32(sf[nf][0], sf[nf][1], sf[nf][2], sf[nf][3],
                         qf[k0][0], qf[k0][1], qf[k0][2], qf[k0][3], b0, b1);
            }
        }

        // score transform
        if (mode != 1) {
            #pragma unroll
            for (int nf = 0; nf < 8; nf++) {
                sf[nf][0] *= scl; sf[nf][1] *= scl;
                sf[nf][2] *= scl; sf[nf][3] *= scl;
            }
        } else {
            #pragma unroll
            for (int nf = 0; nf < 8; nf++) {
                const int cc = nf * 8 + 2 * tig;
                const float tk0 = tks[cc], tk1 = tks[cc + 1];
                #pragma unroll
                for (int q = 0; q < 4; q++) {
                    const float tkv = (q & 1) ? tk1 : tk0;
                    const float ctq = (q & 2) ? ctq1 : ctq0;
                    float am1 = fmaf(-cu, sf[nf][q], fmaf(ctq, tkv, -1.0f));
                    am1 = fmaxf(am1, 1e-7f);
                    float x = am1 * (am1 + 2.0f);
                    float root = x * rsqrtf(x);
                    float dis = rcinv * __logf(am1 + 1.0f + root);
                    sf[nf][q] = __fdividef(1.0f, 1e-6f + dis);
                }
            }
        }

        // causal mask on diagonal tile
        if (kt == qt) {
            #pragma unroll
            for (int nf = 0; nf < 8; nf++) {
                const int cc = nf * 8 + 2 * tig;
                if (cc     > rlo) sf[nf][0] = -1e30f;
                if (cc + 1 > rlo) sf[nf][1] = -1e30f;
                if (cc     > rhi) sf[nf][2] = -1e30f;
                if (cc + 1 > rhi) sf[nf][3] = -1e30f;
            }
        }

        // online softmax (rows rlo, rhi)
        float mx0 = -INFINITY, mx1 = -INFINITY;
        #pragma unroll
        for (int nf = 0; nf < 8; nf++) {
            mx0 = fmaxf(mx0, fmaxf(sf[nf][0], sf[nf][1]));
            mx1 = fmaxf(mx1, fmaxf(sf[nf][2], sf[nf][3]));
        }
        mx0 = fmaxf(mx0, __shfl_xor_sync(0xffffffffu, mx0, 1));
        mx0 = fmaxf(mx0, __shfl_xor_sync(0xffffffffu, mx0, 2));
        mx1 = fmaxf(mx1, __shfl_xor_sync(0xffffffffu, mx1, 1));
        mx1 = fmaxf(mx1, __shfl_xor_sync(0xffffffffu, mx1, 2));
        const float mn0 = fmaxf(m0, mx0), mn1 = fmaxf(m1, mx1);
        const float cr0 = __expf(m0 - mn0), cr1 = __expf(m1 - mn1);

        float s0 = 0.f, s1 = 0.f;
        #pragma unroll
        for (int nf = 0; nf < 8; nf++) {
            float p0 = __expf(sf[nf][0] - mn0);
            float p1 = __expf(sf[nf][1] - mn0);
            float p2 = __expf(sf[nf][2] - mn1);
            float p3 = __expf(sf[nf][3] - mn1);
            s0 += p0 + p1; s1 += p2 + p3;
            const int cc = nf * 8 + 2 * tig;
            Ps[rlo][cc]     = f2tf32(p0);
            Ps[rlo][cc + 1] = f2tf32(p1);
            Ps[rhi][cc]     = f2tf32(p2);
            Ps[rhi][cc + 1] = f2tf32(p3);
            of[nf][0] *= cr0; of[nf][1] *= cr0;
            of[nf][2] *= cr1; of[nf][3] *= cr1;
        }
        s0 += __shfl_xor_sync(0xffffffffu, s0, 1);
        s0 += __shfl_xor_sync(0xffffffffu, s0, 2);
        s1 += __shfl_xor_sync(0xffffffffu, s1, 1);
        s1 += __shfl_xor_sync(0xffffffffu, s1, 2);
        l0 = l0 * cr0 + s0;
        l1 = l1 * cr1 + s1;
        m0 = mn0; m1 = mn1;
        __syncwarp();

        // O += P V   (B operand read straight from row-major Vst)
        #pragma unroll
        for (int k0 = 0; k0 < 8; k0++) {
            const int kb8 = k0 * 8;
            uint32_t a0 = Ps[rlo][kb8 + tig],     a1 = Ps[rhi][kb8 + tig];
            uint32_t a2 = Ps[rlo][kb8 + tig + 4], a3 = Ps[rhi][kb8 + tig + 4];
            #pragma unroll
            for (int nf = 0; nf < 8; nf++) {
                uint32_t b0 = f2tf32(Vst[(kb8 + tig)     * 72 + nf*8 + g]);
                uint32_t b1 = f2tf32(Vst[(kb8 + tig + 4) * 72 + nf*8 + g]);
                mma_tf32(of[nf][0], of[nf][1], of[nf][2], of[nf][3],
                         a0, a1, a2, a3, b0, b1);
            }
        }
        __syncthreads();   // all reads of stage st done before it is re-issued
    }

    // write output rows
    const float il0 = 1.0f / l0, il1 = 1.0f / l1;
    const int rowg_lo = b * T_ + qt * 64 + rlo;
    const int rowg_hi = rowg_lo + 8;
    #pragma unroll
    for (int nf = 0; nf < 8; nf++) {
        const int col = h * HD_ + nf * 8 + 2 * tig;
        float2 vlo; vlo.x = of[nf][0] * il0; vlo.y = of[nf][1] * il0;
        float2 vhi; vhi.x = of[nf][2] * il1; vhi.y = of[nf][3] * il1;
        *(float2*)(g_y + (size_t)rowg_lo * C_ + col) = vlo;
        *(float2*)(g_y + (size_t)rowg_hi * C_ + col) = vhi;
    }
}

// ---------------- launch ----------------
extern "C" void kernel_launch(void* const* d_in, const int* in_sizes, int n_in,
                              void* d_out, int out_size)
{
    const float* x      = (const float*)d_in[0];
    const float* qkv_w  = (const float*)d_in[1];
    const float* proj_w = (const float*)d_in[2];
    const float* proj_b = (const float*)d_in[3];
    const float* curv   = (const float*)d_in[4];
    float* out = (float*)d_out;

    void *pqkv = nullptr, *py = nullptr;
    cudaGetSymbolAddress(&pqkv, g_qkv);
    cudaGetSymbolAddress(&py, g_y);

    cudaFuncSetAttribute(flash_tc,
                         cudaFuncAttributeMaxDynamicSharedMemorySize, FSM_BYTES);
    cudaFuncSetAttribute(mma_gemm<false>,
                         cudaFuncAttributeMaxDynamicSharedMemorySize, GSM_BYTES);
    cudaFuncSetAttribute(mma_gemm<true>,
                         cudaFuncAttributeMaxDynamicSharedMemorySize, GSM_BYTES);

    // 1) qkv = x @ qkv_w^T
    mma_gemm<false><<<dim3(3 * C_ / 128, M_ / 128), 256, GSM_BYTES>>>(
        x, qkv_w, nullptr, (float*)pqkv, M_, 3 * C_, C_);

    // 2) rotary + split + normalize/tq-tk
    rotary_kernel<<<(B_ * H_ * T_) / 8, 256>>>((const float*)pqkv, curv);

    // 3) unified tensor-core attention
    flash_tc<<<dim3(T_ / 64, B_ * H_), 128, FSM_BYTES>>>(curv);

    // 4) out = y @ proj_w^T + proj_b
    mma_gemm<true><<<dim3(C_ / 128, M_ / 128), 256, GSM_BYTES>>>(
        (const float*)py, proj_w, proj_b, out, M_, C_, C_);
}

// round 9
// speedup vs baseline: 3.3558x; 1.1263x over previous
#include <cuda_runtime.h>
#include <math.h>
#include <stdint.h>

#define B_  2
#define T_  2048
#define C_  1024
#define H_  16
#define HD_ 64
#define N1_ 6
#define N2_ 4
#define M_  (B_*T_)   // 4096

// ---------------- scratch (no allocation allowed) ----------------
__device__ float g_qkv[(size_t)M_ * 3 * C_];
__device__ float g_q[(size_t)B_ * H_ * T_ * HD_];
__device__ float g_k[(size_t)B_ * H_ * T_ * HD_];
__device__ float g_v[(size_t)B_ * H_ * T_ * HD_];
__device__ float g_tq[(size_t)B_ * H_ * T_];
__device__ float g_tk[(size_t)B_ * H_ * T_];
__device__ float g_y[(size_t)M_ * C_];
__device__ float g_xt[(size_t)M_ * C_];        // tf32-rounded x
__device__ float g_wq[(size_t)3 * C_ * C_];    // tf32-rounded qkv_w
__device__ float g_wp[(size_t)C_ * C_];        // tf32-rounded proj_w

// ---------------- tf32 helpers ----------------
__device__ __forceinline__ uint32_t f2tf32(float f) {
    uint32_t u;
    asm("cvt.rna.tf32.f32 %0, %1;" : "=r"(u) : "f"(f));
    return u;
}
__device__ __forceinline__ void mma_tf32(float& c0, float& c1, float& c2, float& c3,
                                         uint32_t a0, uint32_t a1, uint32_t a2, uint32_t a3,
                                         uint32_t b0, uint32_t b1) {
    asm volatile(
        "mma.sync.aligned.m16n8k8.row.col.f32.tf32.tf32.f32 "
        "{%0,%1,%2,%3}, {%4,%5,%6,%7}, {%8,%9}, {%0,%1,%2,%3};"
        : "+f"(c0), "+f"(c1), "+f"(c2), "+f"(c3)
        : "r"(a0), "r"(a1), "r"(a2), "r"(a3), "r"(b0), "r"(b1));
}
__device__ __forceinline__ uint32_t smem_u32(const void* p) {
    uint32_t a;
    asm("{ .reg .u64 tmp; cvta.to.shared.u64 tmp, %1; cvt.u32.u64 %0, tmp; }"
        : "=r"(a) : "l"(p));
    return a;
}
__device__ __forceinline__ void cp16(uint32_t dst, const void* src) {
    asm volatile("cp.async.cg.shared.global [%0], [%1], 16;"
                 :: "r"(dst), "l"(src) : "memory");
}
__device__ __forceinline__ void ldm4(uint32_t& r0, uint32_t& r1, uint32_t& r2, uint32_t& r3,
                                     uint32_t addr) {
    asm volatile("ldmatrix.sync.aligned.m8n8.x4.shared.b16 {%0,%1,%2,%3}, [%4];"
                 : "=r"(r0), "=r"(r1), "=r"(r2), "=r"(r3) : "r"(addr));
}

// ---------------- elementwise tf32 rounding pass ----------------
__global__ __launch_bounds__(256) void cvt_tf32_kernel(
    const float4* __restrict__ src, uint4* __restrict__ dst, int n4)
{
    int i = blockIdx.x * 256 + threadIdx.x;
    if (i < n4) {
        float4 f = src[i];
        uint4 u;
        u.x = f2tf32(f.x); u.y = f2tf32(f.y);
        u.z = f2tf32(f.z); u.w = f2tf32(f.w);
        dst[i] = u;
    }
}

// ================= tf32 mma.sync GEMM, 3-stage cp.async, ldmatrix frags ====
// Inputs must already be tf32-rounded. 128x128 tile, 8 warps (2x4), K chunk 32.
#define SPAD   36
#define GSTG   9216
#define GBOFF  4608
#define GSM_BYTES (3 * GSTG * 4)

template<bool BIAS>
__global__ __launch_bounds__(256, 2) void mma_gemm(
    const float* __restrict__ A, const float* __restrict__ Bm,
    const float* __restrict__ bias, float* __restrict__ Cm,
    int M, int N, int K)
{
    extern __shared__ float gsm[];
    const uint32_t sbase = smem_u32(gsm);

    const int tid = threadIdx.x;
    const int wid = tid >> 5, lane = tid & 31;
    const int g = lane >> 2, tig = lane & 3;
    const int warp_m = wid >> 2, warp_n = wid & 3;
    const int bm = blockIdx.y * 128, bn = blockIdx.x * 128;

    const int r  = tid >> 1;
    const int cq = (tid & 1) * 16;
    const float* Ap = A + (size_t)(bm + r) * K + cq;
    const float* Bp = Bm + (size_t)(bn + r) * K + cq;
    const uint32_t sA = sbase + (uint32_t)(r * SPAD + cq) * 4;
    const uint32_t sB = sA + GBOFF * 4;

    // ldmatrix per-lane coordinates
    const int arow  = warp_m * 64 + (lane & 15);       // + mf*16
    const int acol  = (lane >> 4) * 4;                 // + k0
    const int brow  = (lane & 7) + ((lane & 16) ? 8 : 0); // + warp_n*32 + p*16
    const int bcol  = (lane & 8) ? 4 : 0;              // + k0

    float acc[4][4][4];
    #pragma unroll
    for (int i = 0; i < 4; i++)
        #pragma unroll
        for (int j = 0; j < 4; j++)
            #pragma unroll
            for (int q = 0; q < 4; q++) acc[i][j][q] = 0.0f;

    const int nk = K >> 5;

    auto issue = [&](int c, int s) {
        const float* ag = Ap + c * 32;
        const float* bg = Bp + c * 32;
        const uint32_t off = (uint32_t)(s * GSTG) * 4;
        #pragma unroll
        for (int j = 0; j < 4; j++) {
            cp16(sA + off + j * 16, ag + 4 * j);
            cp16(sB + off + j * 16, bg + 4 * j);
        }
        asm volatile("cp.async.commit_group;" ::: "memory");
    };

    issue(0, 0);
    issue(1, 1);

    for (int i = 0; i < nk; i++) {
        if (i + 2 < nk) {
            asm volatile("cp.async.wait_group 1;" ::: "memory");
        } else {
            asm volatile("cp.async.wait_group 0;" ::: "memory");
        }
        __syncthreads();

        if (i + 2 < nk) issue(i + 2, (i + 2) % 3);

        const uint32_t sAs = sbase + (uint32_t)((i % 3) * GSTG) * 4;
        const uint32_t sBs = sAs + GBOFF * 4;
        const uint32_t aAddr0 = sAs + (uint32_t)(arow * SPAD + acol) * 4;
        const uint32_t bAddr0 = sBs + (uint32_t)((warp_n * 32 + brow) * SPAD + bcol) * 4;

        #pragma unroll
        for (int kk = 0; kk < 4; kk++) {
            const int k0 = kk * 8;
            uint32_t afr[4][4], bfr[4][2];
            #pragma unroll
            for (int mf = 0; mf < 4; mf++)
                ldm4(afr[mf][0], afr[mf][1], afr[mf][2], afr[mf][3],
                     aAddr0 + (uint32_t)(mf * 16 * SPAD + k0) * 4);
            #pragma unroll
            for (int p = 0; p < 2; p++)
                ldm4(bfr[2*p][0], bfr[2*p][1], bfr[2*p+1][0], bfr[2*p+1][1],
                     bAddr0 + (uint32_t)(p * 16 * SPAD + k0) * 4);
            #pragma unroll
            for (int mf = 0; mf < 4; mf++)
                #pragma unroll
                for (int nf = 0; nf < 4; nf++)
                    mma_tf32(acc[mf][nf][0], acc[mf][nf][1], acc[mf][nf][2], acc[mf][nf][3],
                             afr[mf][0], afr[mf][1], afr[mf][2], afr[mf][3],
                             bfr[nf][0], bfr[nf][1]);
        }
    }

    #pragma unroll
    for (int mf = 0; mf < 4; mf++) {
        const int row0 = bm + warp_m * 64 + mf * 16 + g;
        #pragma unroll
        for (int nf = 0; nf < 4; nf++) {
            const int col = bn + warp_n * 32 + nf * 8 + tig * 2;
            float b0 = 0.f, b1 = 0.f;
            if (BIAS) { b0 = bias[col]; b1 = bias[col + 1]; }
            float2 v0, v1;
            v0.x = acc[mf][nf][0] + b0; v0.y = acc[mf][nf][1] + b1;
            v1.x = acc[mf][nf][2] + b0; v1.y = acc[mf][nf][3] + b1;
            *(float2*)(Cm + (size_t)row0 * N + col)       = v0;
            *(float2*)(Cm + (size_t)(row0 + 8) * N + col) = v1;
        }
    }
}

// ---------------- rotary + split (writes tf32-rounded q/k/v) ----------------
__global__ __launch_bounds__(256) void rotary_kernel(
    const float* __restrict__ qkv, const float* __restrict__ curv)
{
    const int warp = threadIdx.x >> 5, lane = threadIdx.x & 31;
    const int row = blockIdx.x * 8 + warp;
    const int t = row % T_;
    const int h = (row / T_) % H_;
    const int b = row / (T_ * H_);

    const float* src = qkv + (size_t)(b * T_ + t) * (3 * C_) + h * HD_ + lane;
    float q0 = src[0],        q1 = src[32];
    float k0 = src[C_],       k1 = src[C_ + 32];
    float v0 = src[2 * C_],   v1 = src[2 * C_ + 32];

    const float LOG2_1E4 = 13.287712379549449f;
    float inv_freq = exp2f(-(float)lane * (LOG2_1E4 / 32.0f));
    float fr = (float)t * inv_freq;
    float sn, cs;
    sincosf(fr, &sn, &cs);

    float qa = fmaf(q0, cs,  q1 * sn);
    float qb = fmaf(q1, cs, -q0 * sn);
    float ka = fmaf(k0, cs,  k1 * sn);
    float kb = fmaf(k1, cs, -k0 * sn);

    float sq = qa*qa + qb*qb;
    float sk = ka*ka + kb*kb;
    #pragma unroll
    for (int off = 16; off; off >>= 1) {
        sq += __shfl_xor_sync(0xffffffffu, sq, off);
        sk += __shfl_xor_sync(0xffffffffu, sk, off);
    }

    if (h >= N1_ + N2_) {
        float nq = 1.0f / fmaxf(sqrtf(sq), 1e-12f);
        float nk = 1.0f / fmaxf(sqrtf(sk), 1e-12f);
        qa *= nq; qb *= nq; ka *= nk; kb *= nk;
    } else if (h >= N1_) {
        if (lane == 0) {
            float c = curv[h - N1_];
            g_tq[row] = sqrtf(1.0f / c + sq);
            g_tk[row] = sqrtf(1.0f / c + sk);
        }
    }

    const size_t o = (size_t)row * HD_ + lane;
    g_q[o] = __uint_as_float(f2tf32(qa)); g_q[o + 32] = __uint_as_float(f2tf32(qb));
    g_k[o] = __uint_as_float(f2tf32(ka)); g_k[o + 32] = __uint_as_float(f2tf32(kb));
    g_v[o] = __uint_as_float(f2tf32(v0)); g_v[o + 32] = __uint_as_float(f2tf32(v1));
}

// ---------------- unified tensor-core flash, cp.async + ldmatrix ----------
// grid (T/64, B*H), 128 threads.
// smem bytes: Kst 2x64x68x4 @0 (stage 17408), Vst 2x64x72x4 @34816 (stage 18432),
//             Ps[64][68] u32 @71680, tksh 2x64 f @89088. Total 89600.
#define FK_STG 17408
#define FV_OFF 34816
#define FV_STG 18432
#define FP_OFF 71680
#define FT_OFF 89088
#define FSM_BYTES 89600

__global__ __launch_bounds__(128) void flash_tc(const float* __restrict__ curv)
{
    extern __shared__ char dsm[];
    const uint32_t sb = smem_u32(dsm);
    uint32_t (*Ps)[68] = (uint32_t(*)[68])(dsm + FP_OFF);

    const int bh = blockIdx.y;
    const int qt = (int)gridDim.x - 1 - (int)blockIdx.x;
    const int h = bh % H_, b = bh / H_;
    const int mode = (h < N1_) ? 0 : (h < N1_ + N2_ ? 1 : 2);
    const int tid = threadIdx.x;
    const int lane = tid & 31;
    const int warp = tid >> 5;
    const int g = lane >> 2, tig = lane & 3;
    const int lr = tid >> 1, lc = (tid & 1) * 32;
    const int r0 = warp * 16;
    const int rlo = r0 + g, rhi = rlo + 8;

    // ldmatrix lane coords for K as B-operand (rows = key index, stride 68)
    const int brow = (lane & 7) + ((lane & 16) ? 8 : 0);
    const int bcol = (lane & 8) ? 4 : 0;

    auto issue = [&](int c, int st) {
        if (c <= qt) {
            const float* ksrc = g_k + ((size_t)bh * T_ + c * 64 + lr) * HD_ + lc;
            const float* vsrc = g_v + ((size_t)bh * T_ + c * 64 + lr) * HD_ + lc;
            const uint32_t kdst = sb + st * FK_STG + lr * 272 + (tid & 1) * 128;
            const uint32_t vdst = sb + FV_OFF + st * FV_STG + lr * 288 + (tid & 1) * 128;
            #pragma unroll
            for (int j = 0; j < 8; j++) {
                cp16(kdst + j * 16, ksrc + j * 4);
                cp16(vdst + j * 16, vsrc + j * 4);
            }
            if (mode == 1 && tid < 16)
                cp16(sb + FT_OFF + st * 256 + tid * 16,
                     g_tk + (size_t)bh * T_ + c * 64 + tid * 4);
        }
        asm volatile("cp.async.commit_group;" ::: "memory");
    };

    issue(0, 0);

    // ---- stage Q (already tf32-rounded), preload fragments ----
    {
        const uint4* src = (const uint4*)(g_q + ((size_t)bh * T_ + qt * 64 + lr) * HD_ + lc);
        #pragma unroll
        for (int i = 0; i < 8; i++)
            *(uint4*)&Ps[lr][lc + 4*i] = src[i];
    }
    __syncthreads();
    uint32_t qf[8][4];
    #pragma unroll
    for (int k0 = 0; k0 < 8; k0++) {
        const int kb8 = k0 * 8;
        qf[k0][0] = Ps[rlo][kb8 + tig];
        qf[k0][1] = Ps[rhi][kb8 + tig];
        qf[k0][2] = Ps[rlo][kb8 + tig + 4];
        qf[k0][3] = Ps[rhi][kb8 + tig + 4];
    }
    __syncthreads();

    const float scl = (mode == 0) ? 0.125f : 8.0f;
    float cu = 1.f, rcinv = 1.f, ctq0 = 0.f, ctq1 = 0.f;
    if (mode == 1) {
        cu = curv[h - N1_];
        rcinv = rsqrtf(cu);
        ctq0 = cu * g_tq[(size_t)bh * T_ + qt * 64 + rlo];
        ctq1 = cu * g_tq[(size_t)bh * T_ + qt * 64 + rhi];
    }

    float m0 = -INFINITY, m1 = -INFINITY, l0 = 0.f, l1 = 0.f;
    float of[8][4];
    #pragma unroll
    for (int nf = 0; nf < 8; nf++)
        #pragma unroll
        for (int q = 0; q < 4; q++) of[nf][q] = 0.f;

    for (int kt = 0; kt <= qt; kt++) {
        const int st = kt & 1;
        issue(kt + 1, st ^ 1);
        if (kt + 1 <= qt) {
            asm volatile("cp.async.wait_group 1;" ::: "memory");
        } else {
            asm volatile("cp.async.wait_group 0;" ::: "memory");
        }
        __syncthreads();

        const uint32_t kbase = sb + st * FK_STG + (uint32_t)(brow * 68 + bcol) * 4;
        const uint32_t* Vst = (const uint32_t*)(dsm + FV_OFF + st * FV_STG);
        const float* tks = (const float*)(dsm + FT_OFF + st * 256);

        // S = Q K^T  (K fragments via ldmatrix.x4, 2 nf per call)
        float sf[8][4];
        #pragma unroll
        for (int nf = 0; nf < 8; nf++)
            #pragma unroll
            for (int q = 0; q < 4; q++) sf[nf][q] = 0.f;
        #pragma unroll
        for (int k0 = 0; k0 < 8; k0++) {
            const int kb8 = k0 * 8;
            #pragma unroll
            for (int p = 0; p < 4; p++) {
                uint32_t b00, b01, b10, b11;
                ldm4(b00, b01, b10, b11,
                     kbase + (uint32_t)(p * 16 * 68 + kb8) * 4);
                mma_tf32(sf[2*p][0], sf[2*p][1], sf[2*p][2], sf[2*p][3],
                         qf[k0][0], qf[k0][1], qf[k0][2], qf[k0][3], b00, b01);
                mma_tf32(sf[2*p+1][0], sf[2*p+1][1], sf[2*p+1][2], sf[2*p+1][3],
                         qf[k0][0], qf[k0][1], qf[k0][2], qf[k0][3], b10, b11);
            }
        }

        // score transform
        if (mode != 1) {
            #pragma unroll
            for (int nf = 0; nf < 8; nf++) {
                sf[nf][0] *= scl; sf[nf][1] *= scl;
                sf[nf][2] *= scl; sf[nf][3] *= scl;
            }
        } else {
            #pragma unroll
            for (int nf = 0; nf < 8; nf++) {
                const int cc = nf * 8 + 2 * tig;
                const float tk0 = tks[cc], tk1 = tks[cc + 1];
                #pragma unroll
                for (int q = 0; q < 4; q++) {
                    const float tkv = (q & 1) ? tk1 : tk0;
                    const float ctq = (q & 2) ? ctq1 : ctq0;
                    float am1 = fmaf(-cu, sf[nf][q], fmaf(ctq, tkv, -1.0f));
                    am1 = fmaxf(am1, 1e-7f);
                    float x = am1 * (am1 + 2.0f);
                    float root = x * rsqrtf(x);
                    float dis = rcinv * __logf(am1 + 1.0f + root);
                    sf[nf][q] = __fdividef(1.0f, 1e-6f + dis);
                }
            }
        }

        // causal mask on diagonal tile
        if (kt == qt) {
            #pragma unroll
            for (int nf = 0; nf < 8; nf++) {
                const int cc = nf * 8 + 2 * tig;
                if (cc     > rlo) sf[nf][0] = -1e30f;
                if (cc + 1 > rlo) sf[nf][1] = -1e30f;
                if (cc     > rhi) sf[nf][2] = -1e30f;
                if (cc + 1 > rhi) sf[nf][3] = -1e30f;
            }
        }

        // online softmax
        float mx0 = -INFINITY, mx1 = -INFINITY;
        #pragma unroll
        for (int nf = 0; nf < 8; nf++) {
            mx0 = fmaxf(mx0, fmaxf(sf[nf][0], sf[nf][1]));
            mx1 = fmaxf(mx1, fmaxf(sf[nf][2], sf[nf][3]));
        }
        mx0 = fmaxf(mx0, __shfl_xor_sync(0xffffffffu, mx0, 1));
        mx0 = fmaxf(mx0, __shfl_xor_sync(0xffffffffu, mx0, 2));
        mx1 = fmaxf(mx1, __shfl_xor_sync(0xffffffffu, mx1, 1));
        mx1 = fmaxf(mx1, __shfl_xor_sync(0xffffffffu, mx1, 2));
        const float mn0 = fmaxf(m0, mx0), mn1 = fmaxf(m1, mx1);
        const float cr0 = __expf(m0 - mn0), cr1 = __expf(m1 - mn1);

        float s0 = 0.f, s1 = 0.f;
        #pragma unroll
        for (int nf = 0; nf < 8; nf++) {
            float p0 = __expf(sf[nf][0] - mn0);
            float p1 = __expf(sf[nf][1] - mn0);
            float p2 = __expf(sf[nf][2] - mn1);
            float p3 = __expf(sf[nf][3] - mn1);
            s0 += p0 + p1; s1 += p2 + p3;
            const int cc = nf * 8 + 2 * tig;
            Ps[rlo][cc]     = f2tf32(p0);
            Ps[rlo][cc + 1] = f2tf32(p1);
            Ps[rhi][cc]     = f2tf32(p2);
            Ps[rhi][cc + 1] = f2tf32(p3);
            of[nf][0] *= cr0; of[nf][1] *= cr0;
            of[nf][2] *= cr1; of[nf][3] *= cr1;
        }
        s0 += __shfl_xor_sync(0xffffffffu, s0, 1);
        s0 += __shfl_xor_sync(0xffffffffu, s0, 2);
        s1 += __shfl_xor_sync(0xffffffffu, s1, 1);
        s1 += __shfl_xor_sync(0xffffffffu, s1, 2);
        l0 = l0 * cr0 + s0;
        l1 = l1 * cr1 + s1;
        m0 = mn0; m1 = mn1;
        __syncwarp();

        // O += P V
        #pragma unroll
        for (int k0 = 0; k0 < 8; k0++) {
            const int kb8 = k0 * 8;
            uint32_t a0 = Ps[rlo][kb8 + tig],     a1 = Ps[rhi][kb8 + tig];
            uint32_t a2 = Ps[rlo][kb8 + tig + 4], a3 = Ps[rhi][kb8 + tig + 4];
            #pragma unroll
            for (int nf = 0; nf < 8; nf++) {
                uint32_t b0 = Vst[(kb8 + tig)     * 72 + nf*8 + g];
                uint32_t b1 = Vst[(kb8 + tig + 4) * 72 + nf*8 + g];
                mma_tf32(of[nf][0], of[nf][1], of[nf][2], of[nf][3],
                         a0, a1, a2, a3, b0, b1);
            }
        }
        __syncthreads();
    }

    // write output rows (tf32-rounded, feeds proj GEMM directly)
    const float il0 = 1.0f / l0, il1 = 1.0f / l1;
    const int rowg_lo = b * T_ + qt * 64 + rlo;
    const int rowg_hi = rowg_lo + 8;
    #pragma unroll
    for (int nf = 0; nf < 8; nf++) {
        const int col = h * HD_ + nf * 8 + 2 * tig;
        uint2 vlo, vhi;
        vlo.x = f2tf32(of[nf][0] * il0); vlo.y = f2tf32(of[nf][1] * il0);
        vhi.x = f2tf32(of[nf][2] * il1); vhi.y = f2tf32(of[nf][3] * il1);
        *(uint2*)(g_y + (size_t)rowg_lo * C_ + col) = vlo;
        *(uint2*)(g_y + (size_t)rowg_hi * C_ + col) = vhi;
    }
}

// ---------------- launch ----------------
extern "C" void kernel_launch(void* const* d_in, const int* in_sizes, int n_in,
                              void* d_out, int out_size)
{
    const float* x      = (const float*)d_in[0];
    const float* qkv_w  = (const float*)d_in[1];
    const float* proj_w = (const float*)d_in[2];
    const float* proj_b = (const float*)d_in[3];
    const float* curv   = (const float*)d_in[4];
    float* out = (float*)d_out;

    void *pqkv = nullptr, *py = nullptr, *pxt = nullptr, *pwq = nullptr, *pwp = nullptr;
    cudaGetSymbolAddress(&pqkv, g_qkv);
    cudaGetSymbolAddress(&py, g_y);
    cudaGetSymbolAddress(&pxt, g_xt);
    cudaGetSymbolAddress(&pwq, g_wq);
    cudaGetSymbolAddress(&pwp, g_wp);

    cudaFuncSetAttribute(flash_tc,
                         cudaFuncAttributeMaxDynamicSharedMemorySize, FSM_BYTES);
    cudaFuncSetAttribute(mma_gemm<false>,
                         cudaFuncAttributeMaxDynamicSharedMemorySize, GSM_BYTES);
    cudaFuncSetAttribute(mma_gemm<true>,
                         cudaFuncAttributeMaxDynamicSharedMemorySize, GSM_BYTES);

    // 0) tf32-round GEMM inputs
    cvt_tf32_kernel<<<(M_ * C_ / 4 + 255) / 256, 256>>>(
        (const float4*)x, (uint4*)pxt, M_ * C_ / 4);
    cvt_tf32_kernel<<<(3 * C_ * C_ / 4 + 255) / 256, 256>>>(
        (const float4*)qkv_w, (uint4*)pwq, 3 * C_ * C_ / 4);
    cvt_tf32_kernel<<<(C_ * C_ / 4 + 255) / 256, 256>>>(
        (const float4*)proj_w, (uint4*)pwp, C_ * C_ / 4);

    // 1) qkv = x @ qkv_w^T
    mma_gemm<false><<<dim3(3 * C_ / 128, M_ / 128), 256, GSM_BYTES>>>(
        (const float*)pxt, (const float*)pwq, nullptr, (float*)pqkv, M_, 3 * C_, C_);

    // 2) rotary + split + normalize/tq-tk (writes tf32-rounded q/k/v)
    rotary_kernel<<<(B_ * H_ * T_) / 8, 256>>>((const float*)pqkv, curv);

    // 3) unified tensor-core attention
    flash_tc<<<dim3(T_ / 64, B_ * H_), 128, FSM_BYTES>>>(curv);

    // 4) out = y @ proj_w^T + proj_b
    mma_gemm<true><<<dim3(C_ / 128, M_ / 128), 256, GSM_BYTES>>>(
        (const float*)py, (const float*)pwp, proj_b, out, M_, C_, C_);
}

// round 10
// speedup vs baseline: 3.3903x; 1.0103x over previous
#include <cuda_runtime.h>
#include <math.h>
#include <stdint.h>

#define B_  2
#define T_  2048
#define C_  1024
#define H_  16
#define HD_ 64
#define N1_ 6
#define N2_ 4
#define M_  (B_*T_)   // 4096

// ---------------- scratch (no allocation allowed) ----------------
__device__ float g_qkv[(size_t)M_ * 3 * C_];
__device__ float g_q[(size_t)B_ * H_ * T_ * HD_];
__device__ float g_k[(size_t)B_ * H_ * T_ * HD_];
__device__ float g_v[(size_t)B_ * H_ * T_ * HD_];   // TRANSPOSED: [bh][d][t]
__device__ float g_tq[(size_t)B_ * H_ * T_];
__device__ float g_tk[(size_t)B_ * H_ * T_];
__device__ float g_y[(size_t)M_ * C_];
__device__ float g_xt[(size_t)M_ * C_];
__device__ float g_wq[(size_t)3 * C_ * C_];
__device__ float g_wp[(size_t)C_ * C_];

// ---------------- tf32 helpers ----------------
__device__ __forceinline__ uint32_t f2tf32(float f) {
    uint32_t u;
    asm("cvt.rna.tf32.f32 %0, %1;" : "=r"(u) : "f"(f));
    return u;
}
__device__ __forceinline__ void mma_tf32(float& c0, float& c1, float& c2, float& c3,
                                         uint32_t a0, uint32_t a1, uint32_t a2, uint32_t a3,
                                         uint32_t b0, uint32_t b1) {
    asm volatile(
        "mma.sync.aligned.m16n8k8.row.col.f32.tf32.tf32.f32 "
        "{%0,%1,%2,%3}, {%4,%5,%6,%7}, {%8,%9}, {%0,%1,%2,%3};"
        : "+f"(c0), "+f"(c1), "+f"(c2), "+f"(c3)
        : "r"(a0), "r"(a1), "r"(a2), "r"(a3), "r"(b0), "r"(b1));
}
__device__ __forceinline__ uint32_t smem_u32(const void* p) {
    uint32_t a;
    asm("{ .reg .u64 tmp; cvta.to.shared.u64 tmp, %1; cvt.u32.u64 %0, tmp; }"
        : "=r"(a) : "l"(p));
    return a;
}
__device__ __forceinline__ void cp16(uint32_t dst, const void* src) {
    asm volatile("cp.async.cg.shared.global [%0], [%1], 16;"
                 :: "r"(dst), "l"(src) : "memory");
}
__device__ __forceinline__ void ldm4(uint32_t& r0, uint32_t& r1, uint32_t& r2, uint32_t& r3,
                                     uint32_t addr) {
    asm volatile("ldmatrix.sync.aligned.m8n8.x4.shared.b16 {%0,%1,%2,%3}, [%4];"
                 : "=r"(r0), "=r"(r1), "=r"(r2), "=r"(r3) : "r"(addr));
}

// ---------------- elementwise tf32 rounding pass ----------------
__global__ __launch_bounds__(256) void cvt_tf32_kernel(
    const float4* __restrict__ src, uint4* __restrict__ dst, int n4)
{
    int i = blockIdx.x * 256 + threadIdx.x;
    if (i < n4) {
        float4 f = src[i];
        uint4 u;
        u.x = f2tf32(f.x); u.y = f2tf32(f.y);
        u.z = f2tf32(f.z); u.w = f2tf32(f.w);
        dst[i] = u;
    }
}

// ================= tf32 mma.sync GEMM (R9 passing version) ====
#define SPAD   36
#define GSTG   9216
#define GBOFF  4608
#define GSM_BYTES (3 * GSTG * 4)

template<bool BIAS>
__global__ __launch_bounds__(256, 2) void mma_gemm(
    const float* __restrict__ A, const float* __restrict__ Bm,
    const float* __restrict__ bias, float* __restrict__ Cm,
    int M, int N, int K)
{
    extern __shared__ float gsm[];
    const uint32_t sbase = smem_u32(gsm);

    const int tid = threadIdx.x;
    const int wid = tid >> 5, lane = tid & 31;
    const int g = lane >> 2, tig = lane & 3;
    const int warp_m = wid >> 2, warp_n = wid & 3;
    const int bm = blockIdx.y * 128, bn = blockIdx.x * 128;

    const int r  = tid >> 1;
    const int cq = (tid & 1) * 16;
    const float* Ap = A + (size_t)(bm + r) * K + cq;
    const float* Bp = Bm + (size_t)(bn + r) * K + cq;
    const uint32_t sA = sbase + (uint32_t)(r * SPAD + cq) * 4;
    const uint32_t sB = sA + GBOFF * 4;

    const int arow  = warp_m * 64 + (lane & 15);
    const int acol  = (lane >> 4) * 4;
    const int brow  = (lane & 7) + ((lane & 16) ? 8 : 0);
    const int bcol  = (lane & 8) ? 4 : 0;

    float acc[4][4][4];
    #pragma unroll
    for (int i = 0; i < 4; i++)
        #pragma unroll
        for (int j = 0; j < 4; j++)
            #pragma unroll
            for (int q = 0; q < 4; q++) acc[i][j][q] = 0.0f;

    const int nk = K >> 5;

    auto issue = [&](int c, int s) {
        const float* ag = Ap + c * 32;
        const float* bg = Bp + c * 32;
        const uint32_t off = (uint32_t)(s * GSTG) * 4;
        #pragma unroll
        for (int j = 0; j < 4; j++) {
            cp16(sA + off + j * 16, ag + 4 * j);
            cp16(sB + off + j * 16, bg + 4 * j);
        }
        asm volatile("cp.async.commit_group;" ::: "memory");
    };

    issue(0, 0);
    issue(1, 1);

    for (int i = 0; i < nk; i++) {
        if (i + 2 < nk) {
            asm volatile("cp.async.wait_group 1;" ::: "memory");
        } else {
            asm volatile("cp.async.wait_group 0;" ::: "memory");
        }
        __syncthreads();

        if (i + 2 < nk) issue(i + 2, (i + 2) % 3);

        const uint32_t sAs = sbase + (uint32_t)((i % 3) * GSTG) * 4;
        const uint32_t sBs = sAs + GBOFF * 4;
        const uint32_t aAddr0 = sAs + (uint32_t)(arow * SPAD + acol) * 4;
        const uint32_t bAddr0 = sBs + (uint32_t)((warp_n * 32 + brow) * SPAD + bcol) * 4;

        #pragma unroll
        for (int kk = 0; kk < 4; kk++) {
            const int k0 = kk * 8;
            uint32_t afr[4][4], bfr[4][2];
            #pragma unroll
            for (int mf = 0; mf < 4; mf++)
                ldm4(afr[mf][0], afr[mf][1], afr[mf][2], afr[mf][3],
                     aAddr0 + (uint32_t)(mf * 16 * SPAD + k0) * 4);
            #pragma unroll
            for (int p = 0; p < 2; p++)
                ldm4(bfr[2*p][0], bfr[2*p][1], bfr[2*p+1][0], bfr[2*p+1][1],
                     bAddr0 + (uint32_t)(p * 16 * SPAD + k0) * 4);
            #pragma unroll
            for (int mf = 0; mf < 4; mf++)
                #pragma unroll
                for (int nf = 0; nf < 4; nf++)
                    mma_tf32(acc[mf][nf][0], acc[mf][nf][1], acc[mf][nf][2], acc[mf][nf][3],
                             afr[mf][0], afr[mf][1], afr[mf][2], afr[mf][3],
                             bfr[nf][0], bfr[nf][1]);
        }
    }

    #pragma unroll
    for (int mf = 0; mf < 4; mf++) {
        const int row0 = bm + warp_m * 64 + mf * 16 + g;
        #pragma unroll
        for (int nf = 0; nf < 4; nf++) {
            const int col = bn + warp_n * 32 + nf * 8 + tig * 2;
            float b0 = 0.f, b1 = 0.f;
            if (BIAS) { b0 = bias[col]; b1 = bias[col + 1]; }
            float2 v0, v1;
            v0.x = acc[mf][nf][0] + b0; v0.y = acc[mf][nf][1] + b1;
            v1.x = acc[mf][nf][2] + b0; v1.y = acc[mf][nf][3] + b1;
            *(float2*)(Cm + (size_t)row0 * N + col)       = v0;
            *(float2*)(Cm + (size_t)(row0 + 8) * N + col) = v1;
        }
    }
}

// ---------------- rotary + split; V written TRANSPOSED [bh][d][t] ----------------
__global__ __launch_bounds__(256) void rotary_kernel(
    const float* __restrict__ qkv, const float* __restrict__ curv)
{
    __shared__ float vtile[64][9];
    const int tid = threadIdx.x;
    const int warp = tid >> 5, lane = tid & 31;
    const int row0 = blockIdx.x * 8;
    const int row = row0 + warp;          // (b*H+h)*T + t ; all 8 rows same bh
    const int t = row % T_;
    const int h = (row / T_) % H_;
    const int b = row / (T_ * H_);

    const float* src = qkv + (size_t)(b * T_ + t) * (3 * C_) + h * HD_ + lane;
    float q0 = src[0],        q1 = src[32];
    float k0 = src[C_],       k1 = src[C_ + 32];
    float v0 = src[2 * C_],   v1 = src[2 * C_ + 32];

    const float LOG2_1E4 = 13.287712379549449f;
    float inv_freq = exp2f(-(float)lane * (LOG2_1E4 / 32.0f));
    float fr = (float)t * inv_freq;
    float sn, cs;
    sincosf(fr, &sn, &cs);

    float qa = fmaf(q0, cs,  q1 * sn);
    float qb = fmaf(q1, cs, -q0 * sn);
    float ka = fmaf(k0, cs,  k1 * sn);
    float kb = fmaf(k1, cs, -k0 * sn);

    float sq = qa*qa + qb*qb;
    float sk = ka*ka + kb*kb;
    #pragma unroll
    for (int off = 16; off; off >>= 1) {
        sq += __shfl_xor_sync(0xffffffffu, sq, off);
        sk += __shfl_xor_sync(0xffffffffu, sk, off);
    }

    if (h >= N1_ + N2_) {
        float nq = 1.0f / fmaxf(sqrtf(sq), 1e-12f);
        float nk = 1.0f / fmaxf(sqrtf(sk), 1e-12f);
        qa *= nq; qb *= nq; ka *= nk; kb *= nk;
    } else if (h >= N1_) {
        if (lane == 0) {
            float c = curv[h - N1_];
            g_tq[row] = sqrtf(1.0f / c + sq);
            g_tk[row] = sqrtf(1.0f / c + sk);
        }
    }

    const size_t o = (size_t)row * HD_ + lane;
    g_q[o] = __uint_as_float(f2tf32(qa)); g_q[o + 32] = __uint_as_float(f2tf32(qb));
    g_k[o] = __uint_as_float(f2tf32(ka)); g_k[o + 32] = __uint_as_float(f2tf32(kb));

    // stage V transposed: vtile[d][t-within-block]
    vtile[lane][warp]      = __uint_as_float(f2tf32(v0));
    vtile[lane + 32][warp] = __uint_as_float(f2tf32(v1));
    __syncthreads();

    // write g_v[bh][d][t0..t0+8): thread -> (d, pair of t)
    const int bh0 = row0 / T_;
    const int t0  = row0 % T_;
    const int d   = tid >> 2;
    const int tp  = (tid & 3) * 2;
    float2 val;
    val.x = vtile[d][tp];
    val.y = vtile[d][tp + 1];
    *(float2*)(g_v + ((size_t)bh0 * HD_ + d) * T_ + t0 + tp) = val;
}

// ---------------- unified tensor-core flash, all-ldmatrix operands ----------
// grid (T/64, B*H), 128 threads.
// smem: Kst 2x[64][68] @0 (stage 17408), Vt st 2x[64 d][68 t] @34816 (stage 17408),
//       Ps[64][68] @69632, tksh 2x64 @87040. Total 87552.
#define FK_STG 17408
#define FV_OFF 34816
#define FV_STG 17408
#define FP_OFF 69632
#define FT_OFF 87040
#define FSM_BYTES 87552

__global__ __launch_bounds__(128) void flash_tc(const float* __restrict__ curv)
{
    extern __shared__ char dsm[];
    const uint32_t sb = smem_u32(dsm);
    uint32_t (*Ps)[68] = (uint32_t(*)[68])(dsm + FP_OFF);

    const int bh = blockIdx.y;
    const int qt = (int)gridDim.x - 1 - (int)blockIdx.x;
    const int h = bh % H_, b = bh / H_;
    const int mode = (h < N1_) ? 0 : (h < N1_ + N2_ ? 1 : 2);
    const int tid = threadIdx.x;
    const int lane = tid & 31;
    const int warp = tid >> 5;
    const int g = lane >> 2, tig = lane & 3;
    const int lr = tid >> 1, lc = (tid & 1) * 32;
    const int r0 = warp * 16;
    const int rlo = r0 + g, rhi = rlo + 8;

    // ldmatrix lane coords (B-operand pattern, used for K and V^T)
    const int brow = (lane & 7) + ((lane & 16) ? 8 : 0);
    const int bcol = (lane & 8) ? 4 : 0;
    // A-operand pattern (used for P)
    const int parow = r0 + (lane & 15);
    const int pacol = (lane >> 4) * 4;

    auto issue = [&](int c, int st) {
        if (c <= qt) {
            const float* ksrc = g_k + ((size_t)bh * T_ + c * 64 + lr) * HD_ + lc;
            const float* vsrc = g_v + ((size_t)bh * HD_ + lr) * T_ + c * 64 + lc;
            const uint32_t kdst = sb + st * FK_STG + lr * 272 + (tid & 1) * 128;
            const uint32_t vdst = sb + FV_OFF + st * FV_STG + lr * 272 + (tid & 1) * 128;
            #pragma unroll
            for (int j = 0; j < 8; j++) {
                cp16(kdst + j * 16, ksrc + j * 4);
                cp16(vdst + j * 16, vsrc + j * 4);
            }
            if (mode == 1 && tid < 16)
                cp16(sb + FT_OFF + st * 256 + tid * 16,
                     g_tk + (size_t)bh * T_ + c * 64 + tid * 4);
        }
        asm volatile("cp.async.commit_group;" ::: "memory");
    };

    issue(0, 0);

    // ---- stage Q via Ps, preload fragments ----
    {
        const uint4* src = (const uint4*)(g_q + ((size_t)bh * T_ + qt * 64 + lr) * HD_ + lc);
        #pragma unroll
        for (int i = 0; i < 8; i++)
            *(uint4*)&Ps[lr][lc + 4*i] = src[i];
    }
    __syncthreads();
    uint32_t qf[8][4];
    #pragma unroll
    for (int k0 = 0; k0 < 8; k0++) {
        const int kb8 = k0 * 8;
        qf[k0][0] = Ps[rlo][kb8 + tig];
        qf[k0][1] = Ps[rhi][kb8 + tig];
        qf[k0][2] = Ps[rlo][kb8 + tig + 4];
        qf[k0][3] = Ps[rhi][kb8 + tig + 4];
    }
    __syncthreads();

    const float scl = (mode == 0) ? 0.125f : 8.0f;
    float cu = 1.f, rcinv = 1.f, ctq0 = 0.f, ctq1 = 0.f;
    if (mode == 1) {
        cu = curv[h - N1_];
        rcinv = rsqrtf(cu);
        ctq0 = cu * g_tq[(size_t)bh * T_ + qt * 64 + rlo];
        ctq1 = cu * g_tq[(size_t)bh * T_ + qt * 64 + rhi];
    }

    float m0 = -INFINITY, m1 = -INFINITY, l0 = 0.f, l1 = 0.f;
    float of[8][4];
    #pragma unroll
    for (int nf = 0; nf < 8; nf++)
        #pragma unroll
        for (int q = 0; q < 4; q++) of[nf][q] = 0.f;

    for (int kt = 0; kt <= qt; kt++) {
        const int st = kt & 1;
        issue(kt + 1, st ^ 1);
        if (kt + 1 <= qt) {
            asm volatile("cp.async.wait_group 1;" ::: "memory");
        } else {
            asm volatile("cp.async.wait_group 0;" ::: "memory");
        }
        __syncthreads();

        const uint32_t kbase = sb + st * FK_STG + (uint32_t)(brow * 68 + bcol) * 4;
        const uint32_t vbase = sb + FV_OFF + st * FV_STG + (uint32_t)(brow * 68 + bcol) * 4;
        const uint32_t pbase = sb + FP_OFF + (uint32_t)(parow * 68 + pacol) * 4;
        const float* tks = (const float*)(dsm + FT_OFF + st * 256);

        // S = Q K^T
        float sf[8][4];
        #pragma unroll
        for (int nf = 0; nf < 8; nf++)
            #pragma unroll
            for (int q = 0; q < 4; q++) sf[nf][q] = 0.f;
        #pragma unroll
        for (int k0 = 0; k0 < 8; k0++) {
            const int kb8 = k0 * 8;
            #pragma unroll
            for (int p = 0; p < 4; p++) {
                uint32_t b00, b01, b10, b11;
                ldm4(b00, b01, b10, b11,
                     kbase + (uint32_t)(p * 16 * 68 + kb8) * 4);
                mma_tf32(sf[2*p][0], sf[2*p][1], sf[2*p][2], sf[2*p][3],
                         qf[k0][0], qf[k0][1], qf[k0][2], qf[k0][3], b00, b01);
                mma_tf32(sf[2*p+1][0], sf[2*p+1][1], sf[2*p+1][2], sf[2*p+1][3],
                         qf[k0][0], qf[k0][1], qf[k0][2], qf[k0][3], b10, b11);
            }
        }

        // score transform
        if (mode != 1) {
            #pragma unroll
            for (int nf = 0; nf < 8; nf++) {
                sf[nf][0] *= scl; sf[nf][1] *= scl;
                sf[nf][2] *= scl; sf[nf][3] *= scl;
            }
        } else {
            #pragma unroll
            for (int nf = 0; nf < 8; nf++) {
                const int cc = nf * 8 + 2 * tig;
                const float tk0 = tks[cc], tk1 = tks[cc + 1];
                #pragma unroll
                for (int q = 0; q < 4; q++) {
                    const float tkv = (q & 1) ? tk1 : tk0;
                    const float ctq = (q & 2) ? ctq1 : ctq0;
                    float am1 = fmaf(-cu, sf[nf][q], fmaf(ctq, tkv, -1.0f));
                    am1 = fmaxf(am1, 1e-7f);
                    float x = am1 * (am1 + 2.0f);
                    float root = x * rsqrtf(x);
                    float dis = rcinv * __logf(am1 + 1.0f + root);
                    sf[nf][q] = __fdividef(1.0f, 1e-6f + dis);
                }
            }
        }

        // causal mask on diagonal tile
        if (kt == qt) {
            #pragma unroll
            for (int nf = 0; nf < 8; nf++) {
                const int cc = nf * 8 + 2 * tig;
                if (cc     > rlo) sf[nf][0] = -1e30f;
                if (cc + 1 > rlo) sf[nf][1] = -1e30f;
                if (cc     > rhi) sf[nf][2] = -1e30f;
                if (cc + 1 > rhi) sf[nf][3] = -1e30f;
            }
        }

        // online softmax
        float mx0 = -INFINITY, mx1 = -INFINITY;
        #pragma unroll
        for (int nf = 0; nf < 8; nf++) {
            mx0 = fmaxf(mx0, fmaxf(sf[nf][0], sf[nf][1]));
            mx1 = fmaxf(mx1, fmaxf(sf[nf][2], sf[nf][3]));
        }
        mx0 = fmaxf(mx0, __shfl_xor_sync(0xffffffffu, mx0, 1));
        mx0 = fmaxf(mx0, __shfl_xor_sync(0xffffffffu, mx0, 2));
        mx1 = fmaxf(mx1, __shfl_xor_sync(0xffffffffu, mx1, 1));
        mx1 = fmaxf(mx1, __shfl_xor_sync(0xffffffffu, mx1, 2));
        const float mn0 = fmaxf(m0, mx0), mn1 = fmaxf(m1, mx1);
        const float cr0 = __expf(m0 - mn0), cr1 = __expf(m1 - mn1);

        float s0 = 0.f, s1 = 0.f;
        #pragma unroll
        for (int nf = 0; nf < 8; nf++) {
            float p0 = __expf(sf[nf][0] - mn0);
            float p1 = __expf(sf[nf][1] - mn0);
            float p2 = __expf(sf[nf][2] - mn1);
            float p3 = __expf(sf[nf][3] - mn1);
            s0 += p0 + p1; s1 += p2 + p3;
            const int cc = nf * 8 + 2 * tig;
            Ps[rlo][cc]     = f2tf32(p0);
            Ps[rlo][cc + 1] = f2tf32(p1);
            Ps[rhi][cc]     = f2tf32(p2);
            Ps[rhi][cc + 1] = f2tf32(p3);
            of[nf][0] *= cr0; of[nf][1] *= cr0;
            of[nf][2] *= cr1; of[nf][3] *= cr1;
        }
        s0 += __shfl_xor_sync(0xffffffffu, s0, 1);
        s0 += __shfl_xor_sync(0xffffffffu, s0, 2);
        s1 += __shfl_xor_sync(0xffffffffu, s1, 1);
        s1 += __shfl_xor_sync(0xffffffffu, s1, 2);
        l0 = l0 * cr0 + s0;
        l1 = l1 * cr1 + s1;
        m0 = mn0; m1 = mn1;
        __syncwarp();

        // O += P V : A-frags (P) and B-frags (V^T) both via ldmatrix
        #pragma unroll
        for (int k0 = 0; k0 < 8; k0++) {
            const int kb8 = k0 * 8;
            uint32_t a0, a1, a2, a3;
            ldm4(a0, a1, a2, a3, pbase + (uint32_t)kb8 * 4);
            #pragma unroll
            for (int p = 0; p < 4; p++) {
                uint32_t b00, b01, b10, b11;
                ldm4(b00, b01, b10, b11,
                     vbase + (uint32_t)(p * 16 * 68 + kb8) * 4);
                mma_tf32(of[2*p][0], of[2*p][1], of[2*p][2], of[2*p][3],
                         a0, a1, a2, a3, b00, b01);
                mma_tf32(of[2*p+1][0], of[2*p+1][1], of[2*p+1][2], of[2*p+1][3],
                         a0, a1, a2, a3, b10, b11);
            }
        }
        __syncthreads();
    }

    // write output rows (tf32-rounded, feeds proj GEMM directly)
    const float il0 = 1.0f / l0, il1 = 1.0f / l1;
    const int rowg_lo = b * T_ + qt * 64 + rlo;
    const int rowg_hi = rowg_lo + 8;
    #pragma unroll
    for (int nf = 0; nf < 8; nf++) {
        const int col = h * HD_ + nf * 8 + 2 * tig;
        uint2 vlo, vhi;
        vlo.x = f2tf32(of[nf][0] * il0); vlo.y = f2tf32(of[nf][1] * il0);
        vhi.x = f2tf32(of[nf][2] * il1); vhi.y = f2tf32(of[nf][3] * il1);
        *(uint2*)(g_y + (size_t)rowg_lo * C_ + col) = vlo;
        *(uint2*)(g_y + (size_t)rowg_hi * C_ + col) = vhi;
    }
}

// ---------------- launch ----------------
extern "C" void kernel_launch(void* const* d_in, const int* in_sizes, int n_in,
                              void* d_out, int out_size)
{
    const float* x      = (const float*)d_in[0];
    const float* qkv_w  = (const float*)d_in[1];
    const float* proj_w = (const float*)d_in[2];
    const float* proj_b = (const float*)d_in[3];
    const float* curv   = (const float*)d_in[4];
    float* out = (float*)d_out;

    void *pqkv = nullptr, *py = nullptr, *pxt = nullptr, *pwq = nullptr, *pwp = nullptr;
    cudaGetSymbolAddress(&pqkv, g_qkv);
    cudaGetSymbolAddress(&py, g_y);
    cudaGetSymbolAddress(&pxt, g_xt);
    cudaGetSymbolAddress(&pwq, g_wq);
    cudaGetSymbolAddress(&pwp, g_wp);

    cudaFuncSetAttribute(flash_tc,
                         cudaFuncAttributeMaxDynamicSharedMemorySize, FSM_BYTES);
    cudaFuncSetAttribute(mma_gemm<false>,
                         cudaFuncAttributeMaxDynamicSharedMemorySize, GSM_BYTES);
    cudaFuncSetAttribute(mma_gemm<true>,
                         cudaFuncAttributeMaxDynamicSharedMemorySize, GSM_BYTES);

    // 0) tf32-round GEMM inputs
    cvt_tf32_kernel<<<(M_ * C_ / 4 + 255) / 256, 256>>>(
        (const float4*)x, (uint4*)pxt, M_ * C_ / 4);
    cvt_tf32_kernel<<<(3 * C_ * C_ / 4 + 255) / 256, 256>>>(
        (const float4*)qkv_w, (uint4*)pwq, 3 * C_ * C_ / 4);
    cvt_tf32_kernel<<<(C_ * C_ / 4 + 255) / 256, 256>>>(
        (const float4*)proj_w, (uint4*)pwp, C_ * C_ / 4);

    // 1) qkv = x @ qkv_w^T
    mma_gemm<false><<<dim3(3 * C_ / 128, M_ / 128), 256, GSM_BYTES>>>(
        (const float*)pxt, (const float*)pwq, nullptr, (float*)pqkv, M_, 3 * C_, C_);

    // 2) rotary + split (V written transposed)
    rotary_kernel<<<(B_ * H_ * T_) / 8, 256>>>((const float*)pqkv, curv);

    // 3) unified tensor-core attention
    flash_tc<<<dim3(T_ / 64, B_ * H_), 128, FSM_BYTES>>>(curv);

    // 4) out = y @ proj_w^T + proj_b
    mma_gemm<true><<<dim3(C_ / 128, M_ / 128), 256, GSM_BYTES>>>(
        (const float*)py, (const float*)pwp, proj_b, out, M_, C_, C_);
}

// round 12
// speedup vs baseline: 3.7125x; 1.0950x over previous
#include <cuda_runtime.h>
#include <math.h>
#include <stdint.h>

#define B_  2
#define T_  2048
#define C_  1024
#define H_  16
#define HD_ 64
#define N1_ 6
#define N2_ 4
#define M_  (B_*T_)   // 4096

// ---------------- scratch (no allocation allowed) ----------------
__device__ float g_qkv[(size_t)M_ * 3 * C_];
__device__ float g_q[(size_t)B_ * H_ * T_ * HD_];
__device__ float g_k[(size_t)B_ * H_ * T_ * HD_];
__device__ float g_v[(size_t)B_ * H_ * T_ * HD_];   // TRANSPOSED: [bh][d][t]
__device__ float g_tq[(size_t)B_ * H_ * T_];
__device__ float g_tk[(size_t)B_ * H_ * T_];
__device__ float g_y[(size_t)M_ * C_];
__device__ float g_xt[(size_t)M_ * C_];
__device__ float g_wq[(size_t)3 * C_ * C_];
__device__ float g_wp[(size_t)C_ * C_];

// ---------------- tf32 helpers ----------------
__device__ __forceinline__ uint32_t f2tf32(float f) {
    uint32_t u;
    asm("cvt.rna.tf32.f32 %0, %1;" : "=r"(u) : "f"(f));
    return u;
}
__device__ __forceinline__ void mma_tf32(float& c0, float& c1, float& c2, float& c3,
                                         uint32_t a0, uint32_t a1, uint32_t a2, uint32_t a3,
                                         uint32_t b0, uint32_t b1) {
    asm volatile(
        "mma.sync.aligned.m16n8k8.row.col.f32.tf32.tf32.f32 "
        "{%0,%1,%2,%3}, {%4,%5,%6,%7}, {%8,%9}, {%0,%1,%2,%3};"
        : "+f"(c0), "+f"(c1), "+f"(c2), "+f"(c3)
        : "r"(a0), "r"(a1), "r"(a2), "r"(a3), "r"(b0), "r"(b1));
}
__device__ __forceinline__ uint32_t smem_u32(const void* p) {
    uint32_t a;
    asm("{ .reg .u64 tmp; cvta.to.shared.u64 tmp, %1; cvt.u32.u64 %0, tmp; }"
        : "=r"(a) : "l"(p));
    return a;
}
__device__ __forceinline__ void cp16(uint32_t dst, const void* src) {
    asm volatile("cp.async.cg.shared.global [%0], [%1], 16;"
                 :: "r"(dst), "l"(src) : "memory");
}
__device__ __forceinline__ void ldm4(uint32_t& r0, uint32_t& r1, uint32_t& r2, uint32_t& r3,
                                     uint32_t addr) {
    asm volatile("ldmatrix.sync.aligned.m8n8.x4.shared.b16 {%0,%1,%2,%3}, [%4];"
                 : "=r"(r0), "=r"(r1), "=r"(r2), "=r"(r3) : "r"(addr));
}

// ---------------- elementwise tf32 rounding pass ----------------
__global__ __launch_bounds__(256) void cvt_tf32_kernel(
    const float4* __restrict__ src, uint4* __restrict__ dst, int n4)
{
    int i = blockIdx.x * 256 + threadIdx.x;
    if (i < n4) {
        float4 f = src[i];
        uint4 u;
        u.x = f2tf32(f.x); u.y = f2tf32(f.y);
        u.z = f2tf32(f.z); u.w = f2tf32(f.w);
        dst[i] = u;
    }
}

// ================= tf32 mma.sync GEMM (R9/R10 passing version) ====
#define SPAD   36
#define GSTG   9216
#define GBOFF  4608
#define GSM_BYTES (3 * GSTG * 4)

template<bool BIAS>
__global__ __launch_bounds__(256, 2) void mma_gemm(
    const float* __restrict__ A, const float* __restrict__ Bm,
    const float* __restrict__ bias, float* __restrict__ Cm,
    int M, int N, int K)
{
    extern __shared__ float gsm[];
    const uint32_t sbase = smem_u32(gsm);

    const int tid = threadIdx.x;
    const int wid = tid >> 5, lane = tid & 31;
    const int g = lane >> 2, tig = lane & 3;
    const int warp_m = wid >> 2, warp_n = wid & 3;
    const int bm = blockIdx.y * 128, bn = blockIdx.x * 128;

    const int r  = tid >> 1;
    const int cq = (tid & 1) * 16;
    const float* Ap = A + (size_t)(bm + r) * K + cq;
    const float* Bp = Bm + (size_t)(bn + r) * K + cq;
    const uint32_t sA = sbase + (uint32_t)(r * SPAD + cq) * 4;
    const uint32_t sB = sA + GBOFF * 4;

    const int arow  = warp_m * 64 + (lane & 15);
    const int acol  = (lane >> 4) * 4;
    const int brow  = (lane & 7) + ((lane & 16) ? 8 : 0);
    const int bcol  = (lane & 8) ? 4 : 0;

    float acc[4][4][4];
    #pragma unroll
    for (int i = 0; i < 4; i++)
        #pragma unroll
        for (int j = 0; j < 4; j++)
            #pragma unroll
            for (int q = 0; q < 4; q++) acc[i][j][q] = 0.0f;

    const int nk = K >> 5;

    auto issue = [&](int c, int s) {
        const float* ag = Ap + c * 32;
        const float* bg = Bp + c * 32;
        const uint32_t off = (uint32_t)(s * GSTG) * 4;
        #pragma unroll
        for (int j = 0; j < 4; j++) {
            cp16(sA + off + j * 16, ag + 4 * j);
            cp16(sB + off + j * 16, bg + 4 * j);
        }
        asm volatile("cp.async.commit_group;" ::: "memory");
    };

    issue(0, 0);
    issue(1, 1);

    for (int i = 0; i < nk; i++) {
        if (i + 2 < nk) {
            asm volatile("cp.async.wait_group 1;" ::: "memory");
        } else {
            asm volatile("cp.async.wait_group 0;" ::: "memory");
        }
        __syncthreads();

        if (i + 2 < nk) issue(i + 2, (i + 2) % 3);

        const uint32_t sAs = sbase + (uint32_t)((i % 3) * GSTG) * 4;
        const uint32_t sBs = sAs + GBOFF * 4;
        const uint32_t aAddr0 = sAs + (uint32_t)(arow * SPAD + acol) * 4;
        const uint32_t bAddr0 = sBs + (uint32_t)((warp_n * 32 + brow) * SPAD + bcol) * 4;

        #pragma unroll
        for (int kk = 0; kk < 4; kk++) {
            const int k0 = kk * 8;
            uint32_t afr[4][4], bfr[4][2];
            #pragma unroll
            for (int mf = 0; mf < 4; mf++)
                ldm4(afr[mf][0], afr[mf][1], afr[mf][2], afr[mf][3],
                     aAddr0 + (uint32_t)(mf * 16 * SPAD + k0) * 4);
            #pragma unroll
            for (int p = 0; p < 2; p++)
                ldm4(bfr[2*p][0], bfr[2*p][1], bfr[2*p+1][0], bfr[2*p+1][1],
                     bAddr0 + (uint32_t)(p * 16 * SPAD + k0) * 4);
            #pragma unroll
            for (int mf = 0; mf < 4; mf++)
                #pragma unroll
                for (int nf = 0; nf < 4; nf++)
                    mma_tf32(acc[mf][nf][0], acc[mf][nf][1], acc[mf][nf][2], acc[mf][nf][3],
                             afr[mf][0], afr[mf][1], afr[mf][2], afr[mf][3],
                             bfr[nf][0], bfr[nf][1]);
        }
    }

    #pragma unroll
    for (int mf = 0; mf < 4; mf++) {
        const int row0 = bm + warp_m * 64 + mf * 16 + g;
        #pragma unroll
        for (int nf = 0; nf < 4; nf++) {
            const int col = bn + warp_n * 32 + nf * 8 + tig * 2;
            float b0 = 0.f, b1 = 0.f;
            if (BIAS) { b0 = bias[col]; b1 = bias[col + 1]; }
            float2 v0, v1;
            v0.x = acc[mf][nf][0] + b0; v0.y = acc[mf][nf][1] + b1;
            v1.x = acc[mf][nf][2] + b0; v1.y = acc[mf][nf][3] + b1;
            *(float2*)(Cm + (size_t)row0 * N + col)       = v0;
            *(float2*)(Cm + (size_t)(row0 + 8) * N + col) = v1;
        }
    }
}

// ---------------- rotary + split; V written TRANSPOSED [bh][d][t] ----------------
__global__ __launch_bounds__(256) void rotary_kernel(
    const float* __restrict__ qkv, const float* __restrict__ curv)
{
    __shared__ float vtile[64][9];
    const int tid = threadIdx.x;
    const int warp = tid >> 5, lane = tid & 31;
    const int row0 = blockIdx.x * 8;
    const int row = row0 + warp;
    const int t = row % T_;
    const int h = (row / T_) % H_;
    const int b = row / (T_ * H_);

    const float* src = qkv + (size_t)(b * T_ + t) * (3 * C_) + h * HD_ + lane;
    float q0 = src[0],        q1 = src[32];
    float k0 = src[C_],       k1 = src[C_ + 32];
    float v0 = src[2 * C_],   v1 = src[2 * C_ + 32];

    const float LOG2_1E4 = 13.287712379549449f;
    float inv_freq = exp2f(-(float)lane * (LOG2_1E4 / 32.0f));
    float fr = (float)t * inv_freq;
    float sn, cs;
    sincosf(fr, &sn, &cs);

    float qa = fmaf(q0, cs,  q1 * sn);
    float qb = fmaf(q1, cs, -q0 * sn);
    float ka = fmaf(k0, cs,  k1 * sn);
    float kb = fmaf(k1, cs, -k0 * sn);

    float sq = qa*qa + qb*qb;
    float sk = ka*ka + kb*kb;
    #pragma unroll
    for (int off = 16; off; off >>= 1) {
        sq += __shfl_xor_sync(0xffffffffu, sq, off);
        sk += __shfl_xor_sync(0xffffffffu, sk, off);
    }

    if (h >= N1_ + N2_) {
        float nq = 1.0f / fmaxf(sqrtf(sq), 1e-12f);
        float nk = 1.0f / fmaxf(sqrtf(sk), 1e-12f);
        qa *= nq; qb *= nq; ka *= nk; kb *= nk;
    } else if (h >= N1_) {
        if (lane == 0) {
            float c = curv[h - N1_];
            g_tq[row] = sqrtf(1.0f / c + sq);
            g_tk[row] = sqrtf(1.0f / c + sk);
        }
    }

    const size_t o = (size_t)row * HD_ + lane;
    g_q[o] = __uint_as_float(f2tf32(qa)); g_q[o + 32] = __uint_as_float(f2tf32(qb));
    g_k[o] = __uint_as_float(f2tf32(ka)); g_k[o + 32] = __uint_as_float(f2tf32(kb));

    vtile[lane][warp]      = __uint_as_float(f2tf32(v0));
    vtile[lane + 32][warp] = __uint_as_float(f2tf32(v1));
    __syncthreads();

    const int bh0 = row0 / T_;
    const int t0  = row0 % T_;
    const int d   = tid >> 2;
    const int tp  = (tid & 3) * 2;
    float2 val;
    val.x = vtile[d][tp];
    val.y = vtile[d][tp + 1];
    *(float2*)(g_v + ((size_t)bh0 * HD_ + d) * T_ + t0 + tp) = val;
}

// ---------------- flash: 2 q-tiles (128 queries) per block, shared K/V ----------
// grid (T/128, B*H), 256 threads (8 warps: 0-3 -> qt=2p, 4-7 -> qt=2p+1).
// smem: Kst 2x[64][68] @0, Vt 2x[64][68] @34816, Ps[128][68] @69632,
//       tksh 2x64 @104448. Total 104960.
#define FK_STG 17408
#define FV_OFF 34816
#define FV_STG 17408
#define FP_OFF 69632
#define FT_OFF 104448
#define FSM_BYTES 104960

__global__ __launch_bounds__(256, 2) void flash_tc(const float* __restrict__ curv)
{
    extern __shared__ char dsm[];
    const uint32_t sb = smem_u32(dsm);
    uint32_t (*Ps)[68] = (uint32_t(*)[68])(dsm + FP_OFF);

    const int bh = blockIdx.y;
    const int qtp = (int)gridDim.x - 1 - (int)blockIdx.x;   // heavy blocks first
    const int h = bh % H_, b = bh / H_;
    const int mode = (h < N1_) ? 0 : (h < N1_ + N2_ ? 1 : 2);
    const int tid = threadIdx.x;
    const int lane = tid & 31;
    const int warp = tid >> 5;
    const int wh = warp >> 2;             // 0: qt=2p, 1: qt=2p+1
    const int wq = warp & 3;
    const int qt_own = 2 * qtp + wh;
    const int qt_max = 2 * qtp + 1;
    const int g = lane >> 2, tig = lane & 3;
    const int r0 = wq * 16;
    const int prow_lo = wh * 64 + r0 + g, prow_hi = prow_lo + 8;
    const int rlo = r0 + g, rhi = rlo + 8;   // within own 64-tile

    // ldmatrix lane coords
    const int brow = (lane & 7) + ((lane & 16) ? 8 : 0);
    const int bcol = (lane & 8) ? 4 : 0;
    const int parow = wh * 64 + r0 + (lane & 15);
    const int pacol = (lane >> 4) * 4;

    // K/V tile loader: 256 threads, 16 floats each (4 cp16)
    const int klr = tid >> 2;            // 0..63
    const int kcq = (tid & 3) * 16;      // float col base
    auto issue = [&](int c, int st) {
        if (c <= qt_max) {
            const float* ksrc = g_k + ((size_t)bh * T_ + c * 64 + klr) * HD_ + kcq;
            const float* vsrc = g_v + ((size_t)bh * HD_ + klr) * T_ + c * 64 + kcq;
            const uint32_t kdst = sb + st * FK_STG + klr * 272 + kcq * 4;
            const uint32_t vdst = sb + FV_OFF + st * FV_STG + klr * 272 + kcq * 4;
            #pragma unroll
            for (int j = 0; j < 4; j++) {
                cp16(kdst + j * 16, ksrc + j * 4);
                cp16(vdst + j * 16, vsrc + j * 4);
            }
            if (mode == 1 && tid < 16)
                cp16(sb + FT_OFF + st * 256 + tid * 16,
                     g_tk + (size_t)bh * T_ + c * 64 + tid * 4);
        }
        asm volatile("cp.async.commit_group;" ::: "memory");
    };

    issue(0, 0);

    // ---- stage Q (128 rows) via Ps, preload fragments ----
    {
        const int lr = tid >> 1, lc = (tid & 1) * 32;
        const uint4* src = (const uint4*)(g_q + ((size_t)bh * T_ + qtp * 128 + lr) * HD_ + lc);
        #pragma unroll
        for (int i = 0; i < 8; i++)
            *(uint4*)&Ps[lr][lc + 4*i] = src[i];
    }
    __syncthreads();
    uint32_t qf[8][4];
    #pragma unroll
    for (int k0 = 0; k0 < 8; k0++) {
        const int kb8 = k0 * 8;
        qf[k0][0] = Ps[prow_lo][kb8 + tig];
        qf[k0][1] = Ps[prow_hi][kb8 + tig];
        qf[k0][2] = Ps[prow_lo][kb8 + tig + 4];
        qf[k0][3] = Ps[prow_hi][kb8 + tig + 4];
    }
    __syncthreads();

    const float scl = (mode == 0) ? 0.125f : 8.0f;
    float cu = 1.f, rcinv = 1.f, ctq0 = 0.f, ctq1 = 0.f;
    if (mode == 1) {
        cu = curv[h - N1_];
        rcinv = rsqrtf(cu);
        ctq0 = cu * g_tq[(size_t)bh * T_ + qt_own * 64 + rlo];
        ctq1 = cu * g_tq[(size_t)bh * T_ + qt_own * 64 + rhi];
    }

    float m0 = -INFINITY, m1 = -INFINITY, l0 = 0.f, l1 = 0.f;
    float of[8][4];
    #pragma unroll
    for (int nf = 0; nf < 8; nf++)
        #pragma unroll
        for (int q = 0; q < 4; q++) of[nf][q] = 0.f;

    for (int kt = 0; kt <= qt_max; kt++) {
        const int st = kt & 1;
        issue(kt + 1, st ^ 1);
        if (kt + 1 <= qt_max) {
            asm volatile("cp.async.wait_group 1;" ::: "memory");
        } else {
            asm volatile("cp.async.wait_group 0;" ::: "memory");
        }
        __syncthreads();

        if (kt <= qt_own) {
            const uint32_t kbase = sb + st * FK_STG + (uint32_t)(brow * 68 + bcol) * 4;
            const uint32_t vbase = sb + FV_OFF + st * FV_STG + (uint32_t)(brow * 68 + bcol) * 4;
            const uint32_t pbase = sb + FP_OFF + (uint32_t)(parow * 68 + pacol) * 4;
            const float* tks = (const float*)(dsm + FT_OFF + st * 256);

            // S = Q K^T
            float sf[8][4];
            #pragma unroll
            for (int nf = 0; nf < 8; nf++)
                #pragma unroll
                for (int q = 0; q < 4; q++) sf[nf][q] = 0.f;
            #pragma unroll
            for (int k0 = 0; k0 < 8; k0++) {
                const int kb8 = k0 * 8;
                #pragma unroll
                for (int p = 0; p < 4; p++) {
                    uint32_t b00, b01, b10, b11;
                    ldm4(b00, b01, b10, b11,
                         kbase + (uint32_t)(p * 16 * 68 + kb8) * 4);
                    mma_tf32(sf[2*p][0], sf[2*p][1], sf[2*p][2], sf[2*p][3],
                             qf[k0][0], qf[k0][1], qf[k0][2], qf[k0][3], b00, b01);
                    mma_tf32(sf[2*p+1][0], sf[2*p+1][1], sf[2*p+1][2], sf[2*p+1][3],
                             qf[k0][0], qf[k0][1], qf[k0][2], qf[k0][3], b10, b11);
                }
            }

            // score transform
            if (mode != 1) {
                #pragma unroll
                for (int nf = 0; nf < 8; nf++) {
                    sf[nf][0] *= scl; sf[nf][1] *= scl;
                    sf[nf][2] *= scl; sf[nf][3] *= scl;
                }
            } else {
                #pragma unroll
                for (int nf = 0; nf < 8; nf++) {
                    const int cc = nf * 8 + 2 * tig;
                    const float tk0 = tks[cc], tk1 = tks[cc + 1];
                    #pragma unroll
                    for (int q = 0; q < 4; q++) {
                        const float tkv = (q & 1) ? tk1 : tk0;
                        const float ctq = (q & 2) ? ctq1 : ctq0;
                        float am1 = fmaf(-cu, sf[nf][q], fmaf(ctq, tkv, -1.0f));
                        am1 = fmaxf(am1, 1e-7f);
                        float x = am1 * (am1 + 2.0f);
                        float root = x * rsqrtf(x);
                        float dis = rcinv * __logf(am1 + 1.0f + root);
                        sf[nf][q] = __fdividef(1.0f, 1e-6f + dis);
                    }
                }
            }

            // causal mask on own diagonal tile
            if (kt == qt_own) {
                #pragma unroll
                for (int nf = 0; nf < 8; nf++) {
                    const int cc = nf * 8 + 2 * tig;
                    if (cc     > rlo) sf[nf][0] = -1e30f;
                    if (cc + 1 > rlo) sf[nf][1] = -1e30f;
                    if (cc     > rhi) sf[nf][2] = -1e30f;
                    if (cc + 1 > rhi) sf[nf][3] = -1e30f;
                }
            }

            // online softmax
            float mx0 = -INFINITY, mx1 = -INFINITY;
            #pragma unroll
            for (int nf = 0; nf < 8; nf++) {
                mx0 = fmaxf(mx0, fmaxf(sf[nf][0], sf[nf][1]));
                mx1 = fmaxf(mx1, fmaxf(sf[nf][2], sf[nf][3]));
            }
            mx0 = fmaxf(mx0, __shfl_xor_sync(0xffffffffu, mx0, 1));
            mx0 = fmaxf(mx0, __shfl_xor_sync(0xffffffffu, mx0, 2));
            mx1 = fmaxf(mx1, __shfl_xor_sync(0xffffffffu, mx1, 1));
            mx1 = fmaxf(mx1, __shfl_xor_sync(0xffffffffu, mx1, 2));
            const float mn0 = fmaxf(m0, mx0), mn1 = fmaxf(m1, mx1);
            const float cr0 = __expf(m0 - mn0), cr1 = __expf(m1 - mn1);

            float s0 = 0.f, s1 = 0.f;
            #pragma unroll
            for (int nf = 0; nf < 8; nf++) {
                float p0 = __expf(sf[nf][0] - mn0);
                float p1 = __expf(sf[nf][1] - mn0);
                float p2 = __expf(sf[nf][2] - mn1);
                float p3 = __expf(sf[nf][3] - mn1);
                s0 += p0 + p1; s1 += p2 + p3;
                const int cc = nf * 8 + 2 * tig;
                Ps[prow_lo][cc]     = f2tf32(p0);
                Ps[prow_lo][cc + 1] = f2tf32(p1);
                Ps[prow_hi][cc]     = f2tf32(p2);
                Ps[prow_hi][cc + 1] = f2tf32(p3);
                of[nf][0] *= cr0; of[nf][1] *= cr0;
                of[nf][2] *= cr1; of[nf][3] *= cr1;
            }
            s0 += __shfl_xor_sync(0xffffffffu, s0, 1);
            s0 += __shfl_xor_sync(0xffffffffu, s0, 2);
            s1 += __shfl_xor_sync(0xffffffffu, s1, 1);
            s1 += __shfl_xor_sync(0xffffffffu, s1, 2);
            l0 = l0 * cr0 + s0;
            l1 = l1 * cr1 + s1;
            m0 = mn0; m1 = mn1;
            __syncwarp();

            // O += P V
            #pragma unroll
            for (int k0 = 0; k0 < 8; k0++) {
                const int kb8 = k0 * 8;
                uint32_t a0, a1, a2, a3;
                ldm4(a0, a1, a2, a3, pbase + (uint32_t)kb8 * 4);
                #pragma unroll
                for (int p = 0; p < 4; p++) {
                    uint32_t b00, b01, b10, b11;
                    ldm4(b00, b01, b10, b11,
                         vbase + (uint32_t)(p * 16 * 68 + kb8) * 4);
                    mma_tf32(of[2*p][0], of[2*p][1], of[2*p][2], of[2*p][3],
                             a0, a1, a2, a3, b00, b01);
                    mma_tf32(of[2*p+1][0], of[2*p+1][1], of[2*p+1][2], of[2*p+1][3],
                             a0, a1, a2, a3, b10, b11);
                }
            }
        }
        __syncthreads();
    }

    // write output rows (tf32-rounded, feeds proj GEMM directly)
    const float il0 = 1.0f / l0, il1 = 1.0f / l1;
    const int rowg_lo = b * T_ + qt_own * 64 + rlo;
    const int rowg_hi = rowg_lo + 8;
    #pragma unroll
    for (int nf = 0; nf < 8; nf++) {
        const int col = h * HD_ + nf * 8 + 2 * tig;
        uint2 vlo, vhi;
        vlo.x = f2tf32(of[nf][0] * il0); vlo.y = f2tf32(of[nf][1] * il0);
        vhi.x = f2tf32(of[nf][2] * il1); vhi.y = f2tf32(of[nf][3] * il1);
        *(uint2*)(g_y + (size_t)rowg_lo * C_ + col) = vlo;
        *(uint2*)(g_y + (size_t)rowg_hi * C_ + col) = vhi;
    }
}

// ---------------- launch ----------------
extern "C" void kernel_launch(void* const* d_in, const int* in_sizes, int n_in,
                              void* d_out, int out_size)
{
    const float* x      = (const float*)d_in[0];
    const float* qkv_w  = (const float*)d_in[1];
    const float* proj_w = (const float*)d_in[2];
    const float* proj_b = (const float*)d_in[3];
    const float* curv   = (const float*)d_in[4];
    float* out = (float*)d_out;

    void *pqkv = nullptr, *py = nullptr, *pxt = nullptr, *pwq = nullptr, *pwp = nullptr;
    cudaGetSymbolAddress(&pqkv, g_qkv);
    cudaGetSymbolAddress(&py, g_y);
    cudaGetSymbolAddress(&pxt, g_xt);
    cudaGetSymbolAddress(&pwq, g_wq);
    cudaGetSymbolAddress(&pwp, g_wp);

    cudaFuncSetAttribute(flash_tc,
                         cudaFuncAttributeMaxDynamicSharedMemorySize, FSM_BYTES);
    cudaFuncSetAttribute(mma_gemm<false>,
                         cudaFuncAttributeMaxDynamicSharedMemorySize, GSM_BYTES);
    cudaFuncSetAttribute(mma_gemm<true>,
                         cudaFuncAttributeMaxDynamicSharedMemorySize, GSM_BYTES);

    // 0) tf32-round GEMM inputs
    cvt_tf32_kernel<<<(M_ * C_ / 4 + 255) / 256, 256>>>(
        (const float4*)x, (uint4*)pxt, M_ * C_ / 4);
    cvt_tf32_kernel<<<(3 * C_ * C_ / 4 + 255) / 256, 256>>>(
        (const float4*)qkv_w, (uint4*)pwq, 3 * C_ * C_ / 4);
    cvt_tf32_kernel<<<(C_ * C_ / 4 + 255) / 256, 256>>>(
        (const float4*)proj_w, (uint4*)pwp, C_ * C_ / 4);

    // 1) qkv = x @ qkv_w^T
    mma_gemm<false><<<dim3(3 * C_ / 128, M_ / 128), 256, GSM_BYTES>>>(
        (const float*)pxt, (const float*)pwq, nullptr, (float*)pqkv, M_, 3 * C_, C_);

    // 2) rotary + split (V written transposed)
    rotary_kernel<<<(B_ * H_ * T_) / 8, 256>>>((const float*)pqkv, curv);

    // 3) flash: 2 q-tiles per block, shared K/V
    flash_tc<<<dim3(T_ / 128, B_ * H_), 256, FSM_BYTES>>>(curv);

    // 4) out = y @ proj_w^T + proj_b
    mma_gemm<true><<<dim3(C_ / 128, M_ / 128), 256, GSM_BYTES>>>(
        (const float*)py, (const float*)pwp, proj_b, out, M_, C_, C_);
}